// round 6
// baseline (speedup 1.0000x reference)
#include <cuda_runtime.h>
#include <math.h>

#define DIMC 1024
#define NHC  16
#define HDC  64
#define SEQ  2048
#define BATCH 2
#define NTOK 4096          // BATCH*SEQ
#define EXPN 8
#define TOPK 2
#define HIDC 1024
#define NROUTED (NTOK*TOPK)

// ---------------- scratch (static device globals; no allocation) -------------
__device__ float g_xn [NTOK*DIMC];
__device__ float g_q  [NTOK*DIMC];
__device__ float g_k  [NTOK*DIMC];
__device__ float g_v  [NTOK*DIMC];
__device__ float g_att[NTOK*DIMC];
__device__ float g_h  [NTOK*DIMC];
__device__ float g_hn [NTOK*DIMC];
__device__ float g_sh [NTOK*DIMC];
__device__ float g_e1 [NROUTED*HIDC];
__device__ float g_e3 [NROUTED*HIDC];
__device__ float g_eo [NROUTED*DIMC];
__device__ int   g_cnt [EXPN];
__device__ int   g_off [EXPN+1];
__device__ int   g_fill[EXPN];
__device__ int   g_tok_order[NROUTED];
__device__ int   g_tok_exp [NTOK*TOPK];
__device__ float g_tok_w   [NTOK*TOPK];
__device__ int   g_row_of  [NTOK*TOPK];

// ---------------- RMSNorm ----------------------------------------------------
__global__ void rmsnorm_kernel(const float* __restrict__ x,
                               const float* __restrict__ w,
                               float* __restrict__ y) {
    int row = blockIdx.x;
    const float* xr = x + (size_t)row * DIMC;
    int t = threadIdx.x;
    float v[4];
    float ss = 0.f;
#pragma unroll
    for (int i = 0; i < 4; i++) { v[i] = xr[t + 256*i]; ss += v[i]*v[i]; }
    __shared__ float red[8];
#pragma unroll
    for (int o = 16; o; o >>= 1) ss += __shfl_xor_sync(0xffffffffu, ss, o);
    if ((t & 31) == 0) red[t >> 5] = ss;
    __syncthreads();
    if (t < 8) {
        float s = red[t];
        s += __shfl_xor_sync(0xffu, s, 4);
        s += __shfl_xor_sync(0xffu, s, 2);
        s += __shfl_xor_sync(0xffu, s, 1);
        if (t == 0) red[0] = s;
    }
    __syncthreads();
    float scale = rsqrtf(red[0] * (1.0f/DIMC) + 1e-6f);
    float* yr = y + (size_t)row * DIMC;
#pragma unroll
    for (int i = 0; i < 4; i++) yr[t + 256*i] = v[i] * scale * w[t + 256*i];
}

// ---------------- dense SGEMM: C[M,N] = A[M,K] * B[K,N] (+R) -----------------
__global__ void __launch_bounds__(256) sgemm_dense(
        const float* __restrict__ A, const float* __restrict__ B,
        float* __restrict__ C, const float* __restrict__ R,
        int M, int N, int K) {
    __shared__ float As[8][128];
    __shared__ float Bs[8][128];
    int tid  = threadIdx.x;
    int tx   = tid & 15, ty = tid >> 4;
    int row0 = blockIdx.y * 128;
    int col0 = blockIdx.x * 128;
    int aRow = tid >> 1,  aK   = (tid & 1) << 2;
    int bRow = tid >> 5,  bCol = (tid & 31) << 2;
    bool aValid = (row0 + aRow) < M;
    const float* Aptr = A + (size_t)(row0 + aRow) * K + aK;
    const float* Bptr = B + (size_t)bRow * N + col0 + bCol;
    float acc[8][8];
#pragma unroll
    for (int i = 0; i < 8; i++)
#pragma unroll
        for (int j = 0; j < 8; j++) acc[i][j] = 0.f;

    for (int k0 = 0; k0 < K; k0 += 8) {
        float4 a4 = aValid ? *(const float4*)(Aptr + k0) : make_float4(0,0,0,0);
        As[aK+0][aRow] = a4.x; As[aK+1][aRow] = a4.y;
        As[aK+2][aRow] = a4.z; As[aK+3][aRow] = a4.w;
        *(float4*)&Bs[bRow][bCol] = *(const float4*)(Bptr + (size_t)k0 * N);
        __syncthreads();
#pragma unroll
        for (int k = 0; k < 8; k++) {
            float ra[8], rb[8];
#pragma unroll
            for (int i = 0; i < 8; i++) ra[i] = As[k][ty*8 + i];
#pragma unroll
            for (int j = 0; j < 8; j++) rb[j] = Bs[k][tx*8 + j];
#pragma unroll
            for (int i = 0; i < 8; i++)
#pragma unroll
                for (int j = 0; j < 8; j++)
                    acc[i][j] += ra[i] * rb[j];
        }
        __syncthreads();
    }
#pragma unroll
    for (int i = 0; i < 8; i++) {
        int rr = row0 + ty*8 + i;
        if (rr < M) {
            size_t base = (size_t)rr * N + col0 + tx*8;
            if (R) {
#pragma unroll
                for (int j = 0; j < 8; j++) C[base+j] = acc[i][j] + R[base+j];
            } else {
#pragma unroll
                for (int j = 0; j < 8; j++) C[base+j] = acc[i][j];
            }
        }
    }
}

// ---------------- grouped MoE SGEMM (per-expert segment, optional gather) ----
__global__ void __launch_bounds__(256) sgemm_moe(
        const float* __restrict__ A, const float* __restrict__ Bbase,
        float* __restrict__ C, int useGather, int N, int K) {
    int e = blockIdx.z;
    int segBase = g_off[e];
    int segCnt  = g_off[e+1] - segBase;
    int rt = blockIdx.y * 128;
    if (rt >= segCnt) return;
    const float* B = Bbase + (size_t)e * K * N;

    __shared__ float As[8][128];
    __shared__ float Bs[8][128];
    int tid  = threadIdx.x;
    int tx   = tid & 15, ty = tid >> 4;
    int col0 = blockIdx.x * 128;
    int aRow = tid >> 1,  aK   = (tid & 1) << 2;
    int bRow = tid >> 5,  bCol = (tid & 31) << 2;
    int rloc = rt + aRow;
    bool aValid = rloc < segCnt;
    int arow_idx = 0;
    if (aValid) arow_idx = useGather ? g_tok_order[segBase + rloc] : (segBase + rloc);
    const float* Aptr = A + (size_t)arow_idx * K + aK;
    const float* Bptr = B + (size_t)bRow * N + col0 + bCol;

    float acc[8][8];
#pragma unroll
    for (int i = 0; i < 8; i++)
#pragma unroll
        for (int j = 0; j < 8; j++) acc[i][j] = 0.f;

    for (int k0 = 0; k0 < K; k0 += 8) {
        float4 a4 = aValid ? *(const float4*)(Aptr + k0) : make_float4(0,0,0,0);
        As[aK+0][aRow] = a4.x; As[aK+1][aRow] = a4.y;
        As[aK+2][aRow] = a4.z; As[aK+3][aRow] = a4.w;
        *(float4*)&Bs[bRow][bCol] = *(const float4*)(Bptr + (size_t)k0 * N);
        __syncthreads();
#pragma unroll
        for (int k = 0; k < 8; k++) {
            float ra[8], rb[8];
#pragma unroll
            for (int i = 0; i < 8; i++) ra[i] = As[k][ty*8 + i];
#pragma unroll
            for (int j = 0; j < 8; j++) rb[j] = Bs[k][tx*8 + j];
#pragma unroll
            for (int i = 0; i < 8; i++)
#pragma unroll
                for (int j = 0; j < 8; j++)
                    acc[i][j] += ra[i] * rb[j];
        }
        __syncthreads();
    }
#pragma unroll
    for (int i = 0; i < 8; i++) {
        int rl = rt + ty*8 + i;
        if (rl < segCnt) {
            size_t base = (size_t)(segBase + rl) * N + col0 + tx*8;
#pragma unroll
            for (int j = 0; j < 8; j++) C[base+j] = acc[i][j];
        }
    }
}

// ---------------- RoPE (interleaved complex, applied to q and k) -------------
__global__ void rope_kernel(float* __restrict__ q, float* __restrict__ k,
                            const float* __restrict__ freqs) {
    int idx = blockIdx.x * blockDim.x + threadIdx.x;
    if (idx >= NTOK * NHC * (HDC/2)) return;
    int p = idx & 31;
    int h = (idx >> 5) & 15;
    int t = idx >> 9;
    int s = t & (SEQ - 1);
    float c  = freqs[(s * 32 + p) * 2 + 0];
    float sn = freqs[(s * 32 + p) * 2 + 1];
    size_t base = (size_t)t * DIMC + h * HDC + 2 * p;
    float a = q[base], b = q[base+1];
    q[base]   = a*c - b*sn;
    q[base+1] = a*sn + b*c;
    a = k[base]; b = k[base+1];
    k[base]   = a*c - b*sn;
    k[base+1] = a*sn + b*c;
}

// ---------------- flash attention: 64 q-rows/block, 32-wide KV tiles ---------
__global__ void __launch_bounds__(256) attn_kernel(
        const float* __restrict__ Q, const float* __restrict__ Kp,
        const float* __restrict__ Vp, float* __restrict__ O) {
    int bh = blockIdx.y;
    int b = bh >> 4;
    int h = bh & 15;
    int q0 = blockIdx.x * 64;
    const float* Qb = Q  + (size_t)b*SEQ*DIMC + h*HDC;
    const float* Kb = Kp + (size_t)b*SEQ*DIMC + h*HDC;
    const float* Vb = Vp + (size_t)b*SEQ*DIMC + h*HDC;

    __shared__ float Qs[64][65];
    __shared__ float Ks[32][65];
    __shared__ float Vs[32][65];
    __shared__ float Ps[64][33];

    int tid = threadIdx.x;
    for (int i = tid; i < 64*64; i += 256) {
        int r = i >> 6, c = i & 63;
        Qs[r][c] = Qb[(size_t)(q0 + r) * DIMC + c];
    }
    int r  = tid >> 2;
    int cq = tid & 3;
    float m = -1e30f, l = 0.f;
    float o[16];
#pragma unroll
    for (int i = 0; i < 16; i++) o[i] = 0.f;

    for (int kt = 0; kt < SEQ/32; kt++) {
        __syncthreads();
        for (int i = tid; i < 32*64; i += 256) {
            int rr = i >> 6, c = i & 63;
            Ks[rr][c] = Kb[(size_t)(kt*32 + rr) * DIMC + c];
            Vs[rr][c] = Vb[(size_t)(kt*32 + rr) * DIMC + c];
        }
        __syncthreads();

        float s[8];
#pragma unroll
        for (int jj = 0; jj < 8; jj++) {
            int j = cq*8 + jj;
            float acc = 0.f;
#pragma unroll
            for (int d = 0; d < 64; d++) acc += Qs[r][d] * Ks[j][d];
            s[jj] = acc * 0.125f;   // 1/sqrt(64)
        }
        float tmax = s[0];
#pragma unroll
        for (int jj = 1; jj < 8; jj++) tmax = fmaxf(tmax, s[jj]);
        tmax = fmaxf(tmax, __shfl_xor_sync(0xffffffffu, tmax, 1));
        tmax = fmaxf(tmax, __shfl_xor_sync(0xffffffffu, tmax, 2));
        float mnew  = fmaxf(m, tmax);
        float alpha = __expf(m - mnew);
        float psum = 0.f;
#pragma unroll
        for (int jj = 0; jj < 8; jj++) {
            s[jj] = __expf(s[jj] - mnew);
            psum += s[jj];
            Ps[r][cq*8 + jj] = s[jj];
        }
        psum += __shfl_xor_sync(0xffffffffu, psum, 1);
        psum += __shfl_xor_sync(0xffffffffu, psum, 2);
        l = l * alpha + psum;
        m = mnew;
#pragma unroll
        for (int i = 0; i < 16; i++) o[i] *= alpha;
        __syncthreads();
#pragma unroll 4
        for (int j = 0; j < 32; j++) {
            float pv = Ps[r][j];
#pragma unroll
            for (int i = 0; i < 16; i++) o[i] += pv * Vs[j][cq*16 + i];
        }
    }
    float inv = 1.f / l;
    float* Ob = O + (size_t)b*SEQ*DIMC + h*HDC;
#pragma unroll
    for (int i = 0; i < 16; i++)
        Ob[(size_t)(q0 + r)*DIMC + cq*16 + i] = o[i] * inv;
}

// ---------------- gating: softmax over 8, top-2 ------------------------------
__global__ void gate_kernel(const float* __restrict__ hn,
                            const float* __restrict__ gw) {
    int gt   = (blockIdx.x * blockDim.x + threadIdx.x) >> 5;
    int lane = threadIdx.x & 31;
    if (gt >= NTOK) return;
    const float* row = hn + (size_t)gt * DIMC;
    float vals[32];
#pragma unroll
    for (int i = 0; i < 32; i++) vals[i] = row[lane + 32*i];
    float logits[EXPN];
#pragma unroll
    for (int e = 0; e < EXPN; e++) {
        const float* we = gw + e * DIMC;
        float s = 0.f;
#pragma unroll
        for (int i = 0; i < 32; i++) s += vals[i] * we[lane + 32*i];
        s += __shfl_xor_sync(0xffffffffu, s, 16);
        s += __shfl_xor_sync(0xffffffffu, s, 8);
        s += __shfl_xor_sync(0xffffffffu, s, 4);
        s += __shfl_xor_sync(0xffffffffu, s, 2);
        s += __shfl_xor_sync(0xffffffffu, s, 1);
        logits[e] = s;
    }
    if (lane == 0) {
        float mx = logits[0];
#pragma unroll
        for (int e = 1; e < EXPN; e++) mx = fmaxf(mx, logits[e]);
        float p[EXPN], sum = 0.f;
#pragma unroll
        for (int e = 0; e < EXPN; e++) { p[e] = __expf(logits[e]-mx); sum += p[e]; }
        float inv = 1.f / sum;
#pragma unroll
        for (int e = 0; e < EXPN; e++) p[e] *= inv;
        int e0 = 0;
        for (int e = 1; e < EXPN; e++) if (p[e] > p[e0]) e0 = e;
        int e1 = (e0 == 0) ? 1 : 0;
        for (int e = 0; e < EXPN; e++) { if (e == e0) continue; if (p[e] > p[e1]) e1 = e; }
        g_tok_exp[gt*2+0] = e0;  g_tok_exp[gt*2+1] = e1;
        g_tok_w  [gt*2+0] = p[e0]; g_tok_w[gt*2+1] = p[e1];
        atomicAdd(&g_cnt[e0], 1);
        atomicAdd(&g_cnt[e1], 1);
    }
}

__global__ void zero_cnt_kernel() {
    if (threadIdx.x < EXPN) g_cnt[threadIdx.x] = 0;
}

__global__ void scan_kernel() {
    if (threadIdx.x == 0) {
        int o = 0;
        for (int e = 0; e < EXPN; e++) { g_off[e] = o; g_fill[e] = o; o += g_cnt[e]; }
        g_off[EXPN] = o;
    }
}

__global__ void scatter_kernel() {
    int t = blockIdx.x * blockDim.x + threadIdx.x;
    if (t >= NTOK) return;
#pragma unroll
    for (int k = 0; k < TOPK; k++) {
        int e = g_tok_exp[t*2+k];
        int slot = atomicAdd(&g_fill[e], 1);
        g_tok_order[slot] = t;
        g_row_of[t*2+k] = slot;
    }
}

// ---------------- elementwise silu(a)*b (in place into a) --------------------
__global__ void silumul_kernel(float* __restrict__ a, const float* __restrict__ b,
                               int n) {
    int i = blockIdx.x * blockDim.x + threadIdx.x;
    if (i < n) {
        float x = a[i];
        a[i] = (x / (1.f + __expf(-x))) * b[i];
    }
}

// ---------------- final combine ----------------------------------------------
__global__ void combine_kernel(float* __restrict__ out) {
    int i = blockIdx.x * blockDim.x + threadIdx.x;
    if (i >= NTOK*DIMC) return;
    int t = i >> 10, d = i & 1023;
    int s0 = g_row_of[t*2+0], s1 = g_row_of[t*2+1];
    float w0 = g_tok_w[t*2+0], w1 = g_tok_w[t*2+1];
    float y = w0 * g_eo[(size_t)s0*DIMC + d] + w1 * g_eo[(size_t)s1*DIMC + d];
    out[i] = g_h[i] + g_sh[i] + y;
}

// ---------------- host orchestration -----------------------------------------
extern "C" void kernel_launch(void* const* d_in, const int* in_sizes, int n_in,
                              void* d_out, int out_size) {
    const float* x    = (const float*)d_in[0];
    const float* freqs= (const float*)d_in[1];
    const float* anw  = (const float*)d_in[2];
    const float* wq   = (const float*)d_in[3];
    const float* wk   = (const float*)d_in[4];
    const float* wv   = (const float*)d_in[5];
    const float* wo   = (const float*)d_in[6];
    const float* fnw  = (const float*)d_in[7];
    const float* gw   = (const float*)d_in[8];
    const float* ew1  = (const float*)d_in[9];
    const float* ew2  = (const float*)d_in[10];
    const float* ew3  = (const float*)d_in[11];
    const float* sw1  = (const float*)d_in[12];
    const float* sw2  = (const float*)d_in[13];
    const float* sw3  = (const float*)d_in[14];
    float* out = (float*)d_out;

    float *xn, *q, *k, *v, *att, *h, *hn, *sh, *e1, *e3, *eo;
    cudaGetSymbolAddress((void**)&xn,  g_xn);
    cudaGetSymbolAddress((void**)&q,   g_q);
    cudaGetSymbolAddress((void**)&k,   g_k);
    cudaGetSymbolAddress((void**)&v,   g_v);
    cudaGetSymbolAddress((void**)&att, g_att);
    cudaGetSymbolAddress((void**)&h,   g_h);
    cudaGetSymbolAddress((void**)&hn,  g_hn);
    cudaGetSymbolAddress((void**)&sh,  g_sh);
    cudaGetSymbolAddress((void**)&e1,  g_e1);
    cudaGetSymbolAddress((void**)&e3,  g_e3);
    cudaGetSymbolAddress((void**)&eo,  g_eo);

    dim3 gGemm(DIMC/128, NTOK/128);   // (8, 32)

    // attention sub-block
    rmsnorm_kernel<<<NTOK, 256>>>(x, anw, xn);
    sgemm_dense<<<gGemm, 256>>>(xn, wq, q, nullptr, NTOK, DIMC, DIMC);
    sgemm_dense<<<gGemm, 256>>>(xn, wk, k, nullptr, NTOK, DIMC, DIMC);
    sgemm_dense<<<gGemm, 256>>>(xn, wv, v, nullptr, NTOK, DIMC, DIMC);
    rope_kernel<<<(NTOK*NHC*32 + 255)/256, 256>>>(q, k, freqs);
    attn_kernel<<<dim3(SEQ/64, BATCH*NHC), 256>>>(q, k, v, att);
    sgemm_dense<<<gGemm, 256>>>(att, wo, h, x, NTOK, DIMC, DIMC);

    // MoE sub-block
    rmsnorm_kernel<<<NTOK, 256>>>(h, fnw, hn);
    zero_cnt_kernel<<<1, 32>>>();
    gate_kernel<<<NTOK/8, 256>>>(hn, gw);
    scan_kernel<<<1, 32>>>();
    scatter_kernel<<<NTOK/256, 256>>>();

    dim3 gMoe1(HIDC/128, NROUTED/128, EXPN);
    sgemm_moe<<<gMoe1, 256>>>(hn, ew1, e1, 1, HIDC, DIMC);
    sgemm_moe<<<gMoe1, 256>>>(hn, ew3, e3, 1, HIDC, DIMC);
    silumul_kernel<<<(NROUTED*HIDC)/256, 256>>>(e1, e3, NROUTED*HIDC);
    dim3 gMoe2(DIMC/128, NROUTED/128, EXPN);
    sgemm_moe<<<gMoe2, 256>>>(e1, ew2, eo, 0, DIMC, HIDC);

    // shared expert (reuse q/k as scratch)
    sgemm_dense<<<gGemm, 256>>>(hn, sw1, q, nullptr, NTOK, DIMC, DIMC);
    sgemm_dense<<<gGemm, 256>>>(hn, sw3, k, nullptr, NTOK, DIMC, DIMC);
    silumul_kernel<<<(NTOK*DIMC)/256, 256>>>(q, k, NTOK*DIMC);
    sgemm_dense<<<gGemm, 256>>>(q, sw2, sh, nullptr, NTOK, DIMC, DIMC);

    combine_kernel<<<(NTOK*DIMC)/256, 256>>>(out);
}

// round 8
// speedup vs baseline: 1.2963x; 1.2963x over previous
#include <cuda_runtime.h>
#include <math.h>
#include <stdint.h>

#define DIMC 1024
#define NHC  16
#define HDC  64
#define SEQ  2048
#define BATCH 2
#define NTOK 4096          // BATCH*SEQ
#define EXPN 8
#define TOPK 2
#define HIDC 1024
#define NROUTED (NTOK*TOPK)

// ---------------- scratch (static device globals; no allocation) -------------
__device__ float g_xn [NTOK*DIMC];
__device__ float g_q  [NTOK*DIMC];
__device__ float g_k  [NTOK*DIMC];
__device__ float g_v  [NTOK*DIMC];
__device__ float g_att[NTOK*DIMC];
__device__ float g_h  [NTOK*DIMC];
__device__ float g_hn [NTOK*DIMC];
__device__ float g_sh [NTOK*DIMC];
__device__ float g_e1 [NROUTED*HIDC];
__device__ float g_e3 [NROUTED*HIDC];
__device__ float g_eo [NROUTED*DIMC];
__device__ int   g_cnt [EXPN];
__device__ int   g_off [EXPN+1];
__device__ int   g_fill[EXPN];
__device__ int   g_tok_order[NROUTED];
__device__ int   g_tok_exp [NTOK*TOPK];
__device__ float g_tok_w   [NTOK*TOPK];
__device__ int   g_row_of  [NTOK*TOPK];

// ---------------- tf32 helpers -----------------------------------------------
__device__ __forceinline__ float f2tf32(float x) {
    uint32_t u;
    asm("cvt.rna.tf32.f32 %0, %1;" : "=r"(u) : "f"(x));
    return __uint_as_float(u);
}

__device__ __forceinline__ void mma_tf32(float c[4], const uint32_t a[4],
                                         const uint32_t b[2]) {
    asm volatile(
        "mma.sync.aligned.m16n8k8.row.col.f32.tf32.tf32.f32 "
        "{%0,%1,%2,%3},{%4,%5,%6,%7},{%8,%9},{%0,%1,%2,%3};"
        : "+f"(c[0]), "+f"(c[1]), "+f"(c[2]), "+f"(c[3])
        : "r"(a[0]), "r"(a[1]), "r"(a[2]), "r"(a[3]), "r"(b[0]), "r"(b[1]));
}

// smem strides (floats). Chosen so fragment reads are bank-conflict-free:
//   A: bank = (36*r + c)%32 = (4r+c)%32, r=lane/4 (0..7), c=lane%4 -> distinct
//   B: bank = (136*k + n)%32 = (8k+n)%32, k=lane%4, n=lane/4 -> distinct
#define ASTR 36
#define BSTR 136
#define A_PLANE (128*ASTR)   // 4608 floats
#define B_PLANE (32*BSTR)    // 4352 floats

// ---------------- tensor-core GEMM: C[M,N] = A[M,K] * B[K,N] (+R) ------------
// HIACC=true : 3xTF32 split (fp32-grade accuracy), 71680 B dynamic smem
// HIACC=false: single-pass TF32, 35840 B dynamic smem
template <bool HIACC>
__global__ void __launch_bounds__(256) gemm_tc(
        const float* __restrict__ A, const float* __restrict__ B,
        float* __restrict__ C, const float* __restrict__ R,
        int M, int N, int K) {
    extern __shared__ float sm[];
    float* AsH = sm;
    float* BsH = sm + A_PLANE;
    float* AsL = HIACC ? sm + A_PLANE + B_PLANE : nullptr;
    float* BsL = HIACC ? sm + 2*A_PLANE + B_PLANE : nullptr;

    int tid  = threadIdx.x;
    int warp = tid >> 5, lane = tid & 31;
    int grp = lane >> 2, tig = lane & 3;
    int rowBase = (warp & 1) * 64;
    int colBase = (warp >> 1) * 32;
    int row0 = blockIdx.y * 128;
    int col0 = blockIdx.x * 128;

    int aRow = tid >> 1, aCol = (tid & 1) * 16;
    int bRow = tid >> 3, bCol = (tid & 7) * 16;
    const float* Ag = A + (size_t)(row0 + aRow) * K + aCol;
    const float* Bg = B + (size_t)bRow * N + col0 + bCol;

    float acc[4][4][4];
#pragma unroll
    for (int mt = 0; mt < 4; mt++)
#pragma unroll
        for (int nt = 0; nt < 4; nt++)
#pragma unroll
            for (int i = 0; i < 4; i++) acc[mt][nt][i] = 0.f;

    for (int k0 = 0; k0 < K; k0 += 32) {
#pragma unroll
        for (int i = 0; i < 4; i++) {
            float4 v = *(const float4*)(Ag + k0 + i*4);
            float4 h; h.x=f2tf32(v.x); h.y=f2tf32(v.y); h.z=f2tf32(v.z); h.w=f2tf32(v.w);
            *(float4*)&AsH[aRow*ASTR + aCol + i*4] = h;
            if (HIACC) {
                float4 l; l.x=f2tf32(v.x-h.x); l.y=f2tf32(v.y-h.y);
                l.z=f2tf32(v.z-h.z); l.w=f2tf32(v.w-h.w);
                *(float4*)&AsL[aRow*ASTR + aCol + i*4] = l;
            }
        }
#pragma unroll
        for (int i = 0; i < 4; i++) {
            float4 v = *(const float4*)(Bg + (size_t)k0 * N + i*4);
            float4 h; h.x=f2tf32(v.x); h.y=f2tf32(v.y); h.z=f2tf32(v.z); h.w=f2tf32(v.w);
            *(float4*)&BsH[bRow*BSTR + bCol + i*4] = h;
            if (HIACC) {
                float4 l; l.x=f2tf32(v.x-h.x); l.y=f2tf32(v.y-h.y);
                l.z=f2tf32(v.z-h.z); l.w=f2tf32(v.w-h.w);
                *(float4*)&BsL[bRow*BSTR + bCol + i*4] = l;
            }
        }
        __syncthreads();
#pragma unroll
        for (int kk = 0; kk < 32; kk += 8) {
            uint32_t aH[4][4], aL[4][4], bH[4][2], bL[4][2];
#pragma unroll
            for (int mt = 0; mt < 4; mt++) {
                int r0 = rowBase + mt*16 + grp;
                const float* p = &AsH[r0*ASTR + kk + tig];
                aH[mt][0] = __float_as_uint(p[0]);
                aH[mt][1] = __float_as_uint(p[8*ASTR]);
                aH[mt][2] = __float_as_uint(p[4]);
                aH[mt][3] = __float_as_uint(p[8*ASTR + 4]);
                if (HIACC) {
                    const float* q = &AsL[r0*ASTR + kk + tig];
                    aL[mt][0] = __float_as_uint(q[0]);
                    aL[mt][1] = __float_as_uint(q[8*ASTR]);
                    aL[mt][2] = __float_as_uint(q[4]);
                    aL[mt][3] = __float_as_uint(q[8*ASTR + 4]);
                }
            }
#pragma unroll
            for (int nt = 0; nt < 4; nt++) {
                int c = colBase + nt*8 + grp;
                const float* p = &BsH[(kk + tig)*BSTR + c];
                bH[nt][0] = __float_as_uint(p[0]);
                bH[nt][1] = __float_as_uint(p[4*BSTR]);
                if (HIACC) {
                    const float* q = &BsL[(kk + tig)*BSTR + c];
                    bL[nt][0] = __float_as_uint(q[0]);
                    bL[nt][1] = __float_as_uint(q[4*BSTR]);
                }
            }
#pragma unroll
            for (int nt = 0; nt < 4; nt++)
#pragma unroll
                for (int mt = 0; mt < 4; mt++) {
                    mma_tf32(acc[mt][nt], aH[mt], bH[nt]);
                    if (HIACC) {
                        mma_tf32(acc[mt][nt], aH[mt], bL[nt]);
                        mma_tf32(acc[mt][nt], aL[mt], bH[nt]);
                    }
                }
        }
        __syncthreads();
    }

#pragma unroll
    for (int mt = 0; mt < 4; mt++) {
        int r = row0 + rowBase + mt*16 + grp;
#pragma unroll
        for (int nt = 0; nt < 4; nt++) {
            int c = col0 + colBase + nt*8 + tig*2;
            size_t o0 = (size_t)r * N + c;
            size_t o1 = (size_t)(r + 8) * N + c;
            float2 v0 = make_float2(acc[mt][nt][0], acc[mt][nt][1]);
            float2 v1 = make_float2(acc[mt][nt][2], acc[mt][nt][3]);
            if (R) {
                v0.x += R[o0]; v0.y += R[o0+1];
                v1.x += R[o1]; v1.y += R[o1+1];
            }
            *(float2*)(C + o0) = v0;
            *(float2*)(C + o1) = v1;
        }
    }
}

// ---------------- grouped MoE tensor-core GEMM (single-pass TF32) ------------
__global__ void __launch_bounds__(256) gemm_tc_moe(
        const float* __restrict__ A, const float* __restrict__ Bbase,
        float* __restrict__ C, int useGather, int N, int K) {
    int e = blockIdx.z;
    int segBase = g_off[e];
    int segCnt  = g_off[e+1] - segBase;
    int rt = blockIdx.y * 128;
    if (rt >= segCnt) return;
    const float* B = Bbase + (size_t)e * K * N;

    extern __shared__ float sm[];
    float* AsH = sm;
    float* BsH = sm + A_PLANE;

    int tid  = threadIdx.x;
    int warp = tid >> 5, lane = tid & 31;
    int grp = lane >> 2, tig = lane & 3;
    int rowBase = (warp & 1) * 64;
    int colBase = (warp >> 1) * 32;
    int col0 = blockIdx.x * 128;

    int aRow = tid >> 1, aCol = (tid & 1) * 16;
    int bRow = tid >> 3, bCol = (tid & 7) * 16;
    int rl0 = rt + aRow;
    bool aValid = rl0 < segCnt;
    int arow_idx = 0;
    if (aValid) arow_idx = useGather ? g_tok_order[segBase + rl0] : (segBase + rl0);
    const float* Ag = A + (size_t)arow_idx * K + aCol;
    const float* Bg = B + (size_t)bRow * N + col0 + bCol;

    float acc[4][4][4];
#pragma unroll
    for (int mt = 0; mt < 4; mt++)
#pragma unroll
        for (int nt = 0; nt < 4; nt++)
#pragma unroll
            for (int i = 0; i < 4; i++) acc[mt][nt][i] = 0.f;

    for (int k0 = 0; k0 < K; k0 += 32) {
#pragma unroll
        for (int i = 0; i < 4; i++) {
            float4 v = aValid ? *(const float4*)(Ag + k0 + i*4)
                              : make_float4(0.f,0.f,0.f,0.f);
            float4 h; h.x=f2tf32(v.x); h.y=f2tf32(v.y); h.z=f2tf32(v.z); h.w=f2tf32(v.w);
            *(float4*)&AsH[aRow*ASTR + aCol + i*4] = h;
        }
#pragma unroll
        for (int i = 0; i < 4; i++) {
            float4 v = *(const float4*)(Bg + (size_t)k0 * N + i*4);
            float4 h; h.x=f2tf32(v.x); h.y=f2tf32(v.y); h.z=f2tf32(v.z); h.w=f2tf32(v.w);
            *(float4*)&BsH[bRow*BSTR + bCol + i*4] = h;
        }
        __syncthreads();
#pragma unroll
        for (int kk = 0; kk < 32; kk += 8) {
            uint32_t aH[4][4], bH[4][2];
#pragma unroll
            for (int mt = 0; mt < 4; mt++) {
                int r0 = rowBase + mt*16 + grp;
                const float* p = &AsH[r0*ASTR + kk + tig];
                aH[mt][0] = __float_as_uint(p[0]);
                aH[mt][1] = __float_as_uint(p[8*ASTR]);
                aH[mt][2] = __float_as_uint(p[4]);
                aH[mt][3] = __float_as_uint(p[8*ASTR + 4]);
            }
#pragma unroll
            for (int nt = 0; nt < 4; nt++) {
                int c = colBase + nt*8 + grp;
                const float* p = &BsH[(kk + tig)*BSTR + c];
                bH[nt][0] = __float_as_uint(p[0]);
                bH[nt][1] = __float_as_uint(p[4*BSTR]);
            }
#pragma unroll
            for (int nt = 0; nt < 4; nt++)
#pragma unroll
                for (int mt = 0; mt < 4; mt++)
                    mma_tf32(acc[mt][nt], aH[mt], bH[nt]);
        }
        __syncthreads();
    }

#pragma unroll
    for (int mt = 0; mt < 4; mt++) {
        int rl = rt + rowBase + mt*16 + grp;
#pragma unroll
        for (int nt = 0; nt < 4; nt++) {
            int c = col0 + colBase + nt*8 + tig*2;
            if (rl < segCnt) {
                size_t o = (size_t)(segBase + rl) * N + c;
                *(float2*)(C + o) = make_float2(acc[mt][nt][0], acc[mt][nt][1]);
            }
            if (rl + 8 < segCnt) {
                size_t o = (size_t)(segBase + rl + 8) * N + c;
                *(float2*)(C + o) = make_float2(acc[mt][nt][2], acc[mt][nt][3]);
            }
        }
    }
}

// ---------------- RMSNorm ----------------------------------------------------
__global__ void rmsnorm_kernel(const float* __restrict__ x,
                               const float* __restrict__ w,
                               float* __restrict__ y) {
    int row = blockIdx.x;
    const float* xr = x + (size_t)row * DIMC;
    int t = threadIdx.x;
    float v[4];
    float ss = 0.f;
#pragma unroll
    for (int i = 0; i < 4; i++) { v[i] = xr[t + 256*i]; ss += v[i]*v[i]; }
    __shared__ float red[8];
#pragma unroll
    for (int o = 16; o; o >>= 1) ss += __shfl_xor_sync(0xffffffffu, ss, o);
    if ((t & 31) == 0) red[t >> 5] = ss;
    __syncthreads();
    if (t < 8) {
        float s = red[t];
        s += __shfl_xor_sync(0xffu, s, 4);
        s += __shfl_xor_sync(0xffu, s, 2);
        s += __shfl_xor_sync(0xffu, s, 1);
        if (t == 0) red[0] = s;
    }
    __syncthreads();
    float scale = rsqrtf(red[0] * (1.0f/DIMC) + 1e-6f);
    float* yr = y + (size_t)row * DIMC;
#pragma unroll
    for (int i = 0; i < 4; i++) yr[t + 256*i] = v[i] * scale * w[t + 256*i];
}

// ---------------- RoPE (interleaved complex, applied to q and k) -------------
__global__ void rope_kernel(float* __restrict__ q, float* __restrict__ k,
                            const float* __restrict__ freqs) {
    int idx = blockIdx.x * blockDim.x + threadIdx.x;
    if (idx >= NTOK * NHC * (HDC/2)) return;
    int p = idx & 31;
    int h = (idx >> 5) & 15;
    int t = idx >> 9;
    int s = t & (SEQ - 1);
    float c  = freqs[(s * 32 + p) * 2 + 0];
    float sn = freqs[(s * 32 + p) * 2 + 1];
    size_t base = (size_t)t * DIMC + h * HDC + 2 * p;
    float a = q[base], b = q[base+1];
    q[base]   = a*c - b*sn;
    q[base+1] = a*sn + b*c;
    a = k[base]; b = k[base+1];
    k[base]   = a*c - b*sn;
    k[base+1] = a*sn + b*c;
}

// ---------------- flash attention: 64 q-rows/block, 32-wide KV tiles ---------
__global__ void __launch_bounds__(256) attn_kernel(
        const float* __restrict__ Q, const float* __restrict__ Kp,
        const float* __restrict__ Vp, float* __restrict__ O) {
    int bh = blockIdx.y;
    int b = bh >> 4;
    int h = bh & 15;
    int q0 = blockIdx.x * 64;
    const float* Qb = Q  + (size_t)b*SEQ*DIMC + h*HDC;
    const float* Kb = Kp + (size_t)b*SEQ*DIMC + h*HDC;
    const float* Vb = Vp + (size_t)b*SEQ*DIMC + h*HDC;

    __shared__ float Qs[64][65];
    __shared__ float Ks[32][65];
    __shared__ float Vs[32][65];
    __shared__ float Ps[64][33];

    int tid = threadIdx.x;
    for (int i = tid; i < 64*64; i += 256) {
        int r = i >> 6, c = i & 63;
        Qs[r][c] = Qb[(size_t)(q0 + r) * DIMC + c];
    }
    int r  = tid >> 2;
    int cq = tid & 3;
    float m = -1e30f, l = 0.f;
    float o[16];
#pragma unroll
    for (int i = 0; i < 16; i++) o[i] = 0.f;

    for (int kt = 0; kt < SEQ/32; kt++) {
        __syncthreads();
        for (int i = tid; i < 32*64; i += 256) {
            int rr = i >> 6, c = i & 63;
            Ks[rr][c] = Kb[(size_t)(kt*32 + rr) * DIMC + c];
            Vs[rr][c] = Vb[(size_t)(kt*32 + rr) * DIMC + c];
        }
        __syncthreads();

        float s[8];
#pragma unroll
        for (int jj = 0; jj < 8; jj++) {
            int j = cq*8 + jj;
            float acc = 0.f;
#pragma unroll
            for (int d = 0; d < 64; d++) acc += Qs[r][d] * Ks[j][d];
            s[jj] = acc * 0.125f;   // 1/sqrt(64)
        }
        float tmax = s[0];
#pragma unroll
        for (int jj = 1; jj < 8; jj++) tmax = fmaxf(tmax, s[jj]);
        tmax = fmaxf(tmax, __shfl_xor_sync(0xffffffffu, tmax, 1));
        tmax = fmaxf(tmax, __shfl_xor_sync(0xffffffffu, tmax, 2));
        float mnew  = fmaxf(m, tmax);
        float alpha = __expf(m - mnew);
        float psum = 0.f;
#pragma unroll
        for (int jj = 0; jj < 8; jj++) {
            s[jj] = __expf(s[jj] - mnew);
            psum += s[jj];
            Ps[r][cq*8 + jj] = s[jj];
        }
        psum += __shfl_xor_sync(0xffffffffu, psum, 1);
        psum += __shfl_xor_sync(0xffffffffu, psum, 2);
        l = l * alpha + psum;
        m = mnew;
#pragma unroll
        for (int i = 0; i < 16; i++) o[i] *= alpha;
        __syncthreads();
#pragma unroll 4
        for (int j = 0; j < 32; j++) {
            float pv = Ps[r][j];
#pragma unroll
            for (int i = 0; i < 16; i++) o[i] += pv * Vs[j][cq*16 + i];
        }
    }
    float inv = 1.f / l;
    float* Ob = O + (size_t)b*SEQ*DIMC + h*HDC;
#pragma unroll
    for (int i = 0; i < 16; i++)
        Ob[(size_t)(q0 + r)*DIMC + cq*16 + i] = o[i] * inv;
}

// ---------------- gating: softmax over 8, top-2 ------------------------------
__global__ void gate_kernel(const float* __restrict__ hn,
                            const float* __restrict__ gw) {
    int gt   = (blockIdx.x * blockDim.x + threadIdx.x) >> 5;
    int lane = threadIdx.x & 31;
    if (gt >= NTOK) return;
    const float* row = hn + (size_t)gt * DIMC;
    float vals[32];
#pragma unroll
    for (int i = 0; i < 32; i++) vals[i] = row[lane + 32*i];
    float logits[EXPN];
#pragma unroll
    for (int e = 0; e < EXPN; e++) {
        const float* we = gw + e * DIMC;
        float s = 0.f;
#pragma unroll
        for (int i = 0; i < 32; i++) s += vals[i] * we[lane + 32*i];
        s += __shfl_xor_sync(0xffffffffu, s, 16);
        s += __shfl_xor_sync(0xffffffffu, s, 8);
        s += __shfl_xor_sync(0xffffffffu, s, 4);
        s += __shfl_xor_sync(0xffffffffu, s, 2);
        s += __shfl_xor_sync(0xffffffffu, s, 1);
        logits[e] = s;
    }
    if (lane == 0) {
        float mx = logits[0];
#pragma unroll
        for (int e = 1; e < EXPN; e++) mx = fmaxf(mx, logits[e]);
        float p[EXPN], sum = 0.f;
#pragma unroll
        for (int e = 0; e < EXPN; e++) { p[e] = __expf(logits[e]-mx); sum += p[e]; }
        float inv = 1.f / sum;
#pragma unroll
        for (int e = 0; e < EXPN; e++) p[e] *= inv;
        int e0 = 0;
        for (int e = 1; e < EXPN; e++) if (p[e] > p[e0]) e0 = e;
        int e1 = (e0 == 0) ? 1 : 0;
        for (int e = 0; e < EXPN; e++) { if (e == e0) continue; if (p[e] > p[e1]) e1 = e; }
        g_tok_exp[gt*2+0] = e0;  g_tok_exp[gt*2+1] = e1;
        g_tok_w  [gt*2+0] = p[e0]; g_tok_w[gt*2+1] = p[e1];
        atomicAdd(&g_cnt[e0], 1);
        atomicAdd(&g_cnt[e1], 1);
    }
}

__global__ void zero_cnt_kernel() {
    if (threadIdx.x < EXPN) g_cnt[threadIdx.x] = 0;
}

__global__ void scan_kernel() {
    if (threadIdx.x == 0) {
        int o = 0;
        for (int e = 0; e < EXPN; e++) { g_off[e] = o; g_fill[e] = o; o += g_cnt[e]; }
        g_off[EXPN] = o;
    }
}

__global__ void scatter_kernel() {
    int t = blockIdx.x * blockDim.x + threadIdx.x;
    if (t >= NTOK) return;
#pragma unroll
    for (int k = 0; k < TOPK; k++) {
        int e = g_tok_exp[t*2+k];
        int slot = atomicAdd(&g_fill[e], 1);
        g_tok_order[slot] = t;
        g_row_of[t*2+k] = slot;
    }
}

// ---------------- elementwise silu(a)*b (in place into a) --------------------
__global__ void silumul_kernel(float* __restrict__ a, const float* __restrict__ b,
                               int n) {
    int i = blockIdx.x * blockDim.x + threadIdx.x;
    if (i < n) {
        float x = a[i];
        a[i] = (x / (1.f + __expf(-x))) * b[i];
    }
}

// ---------------- final combine ----------------------------------------------
__global__ void combine_kernel(float* __restrict__ out) {
    int i = blockIdx.x * blockDim.x + threadIdx.x;
    if (i >= NTOK*DIMC) return;
    int t = i >> 10, d = i & 1023;
    int s0 = g_row_of[t*2+0], s1 = g_row_of[t*2+1];
    float w0 = g_tok_w[t*2+0], w1 = g_tok_w[t*2+1];
    float y = w0 * g_eo[(size_t)s0*DIMC + d] + w1 * g_eo[(size_t)s1*DIMC + d];
    out[i] = g_h[i] + g_sh[i] + y;
}

// ---------------- host orchestration -----------------------------------------
#define SMEM_HI ((2*A_PLANE + 2*B_PLANE) * 4)   // 71680 B
#define SMEM_LO ((A_PLANE + B_PLANE) * 4)       // 35840 B

extern "C" void kernel_launch(void* const* d_in, const int* in_sizes, int n_in,
                              void* d_out, int out_size) {
    const float* x    = (const float*)d_in[0];
    const float* freqs= (const float*)d_in[1];
    const float* anw  = (const float*)d_in[2];
    const float* wq   = (const float*)d_in[3];
    const float* wk   = (const float*)d_in[4];
    const float* wv   = (const float*)d_in[5];
    const float* wo   = (const float*)d_in[6];
    const float* fnw  = (const float*)d_in[7];
    const float* gw   = (const float*)d_in[8];
    const float* ew1  = (const float*)d_in[9];
    const float* ew2  = (const float*)d_in[10];
    const float* ew3  = (const float*)d_in[11];
    const float* sw1  = (const float*)d_in[12];
    const float* sw2  = (const float*)d_in[13];
    const float* sw3  = (const float*)d_in[14];
    float* out = (float*)d_out;

    float *xn, *q, *k, *v, *att, *h, *hn, *sh, *e1, *e3, *eo;
    cudaGetSymbolAddress((void**)&xn,  g_xn);
    cudaGetSymbolAddress((void**)&q,   g_q);
    cudaGetSymbolAddress((void**)&k,   g_k);
    cudaGetSymbolAddress((void**)&v,   g_v);
    cudaGetSymbolAddress((void**)&att, g_att);
    cudaGetSymbolAddress((void**)&h,   g_h);
    cudaGetSymbolAddress((void**)&hn,  g_hn);
    cudaGetSymbolAddress((void**)&sh,  g_sh);
    cudaGetSymbolAddress((void**)&e1,  g_e1);
    cudaGetSymbolAddress((void**)&e3,  g_e3);
    cudaGetSymbolAddress((void**)&eo,  g_eo);

    static int attr_done = 0;
    if (!attr_done) {
        cudaFuncSetAttribute(gemm_tc<true>,
            cudaFuncAttributeMaxDynamicSharedMemorySize, SMEM_HI);
        cudaFuncSetAttribute(gemm_tc<false>,
            cudaFuncAttributeMaxDynamicSharedMemorySize, SMEM_LO);
        cudaFuncSetAttribute(gemm_tc_moe,
            cudaFuncAttributeMaxDynamicSharedMemorySize, SMEM_LO);
        attr_done = 1;
    }

    dim3 gGemm(DIMC/128, NTOK/128);   // (8, 32)

    // attention sub-block (3xTF32: routing-critical accuracy)
    rmsnorm_kernel<<<NTOK, 256>>>(x, anw, xn);
    gemm_tc<true><<<gGemm, 256, SMEM_HI>>>(xn, wq, q, nullptr, NTOK, DIMC, DIMC);
    gemm_tc<true><<<gGemm, 256, SMEM_HI>>>(xn, wk, k, nullptr, NTOK, DIMC, DIMC);
    gemm_tc<true><<<gGemm, 256, SMEM_HI>>>(xn, wv, v, nullptr, NTOK, DIMC, DIMC);
    rope_kernel<<<(NTOK*NHC*32 + 255)/256, 256>>>(q, k, freqs);
    attn_kernel<<<dim3(SEQ/64, BATCH*NHC), 256>>>(q, k, v, att);
    gemm_tc<true><<<gGemm, 256, SMEM_HI>>>(att, wo, h, x, NTOK, DIMC, DIMC);

    // MoE sub-block
    rmsnorm_kernel<<<NTOK, 256>>>(h, fnw, hn);
    zero_cnt_kernel<<<1, 32>>>();
    gate_kernel<<<NTOK/8, 256>>>(hn, gw);
    scan_kernel<<<1, 32>>>();
    scatter_kernel<<<NTOK/256, 256>>>();

    dim3 gMoe1(HIDC/128, NROUTED/128, EXPN);
    gemm_tc_moe<<<gMoe1, 256, SMEM_LO>>>(hn, ew1, e1, 1, HIDC, DIMC);
    gemm_tc_moe<<<gMoe1, 256, SMEM_LO>>>(hn, ew3, e3, 1, HIDC, DIMC);
    silumul_kernel<<<(NROUTED*HIDC)/256, 256>>>(e1, e3, NROUTED*HIDC);
    dim3 gMoe2(DIMC/128, NROUTED/128, EXPN);
    gemm_tc_moe<<<gMoe2, 256, SMEM_LO>>>(e1, ew2, eo, 0, DIMC, HIDC);

    // shared expert (single-pass TF32; output-only path)
    gemm_tc<false><<<gGemm, 256, SMEM_LO>>>(hn, sw1, q, nullptr, NTOK, DIMC, DIMC);
    gemm_tc<false><<<gGemm, 256, SMEM_LO>>>(hn, sw3, k, nullptr, NTOK, DIMC, DIMC);
    silumul_kernel<<<(NTOK*DIMC)/256, 256>>>(q, k, NTOK*DIMC);
    gemm_tc<false><<<gGemm, 256, SMEM_LO>>>(q, sw2, sh, nullptr, NTOK, DIMC, DIMC);

    combine_kernel<<<(NTOK*DIMC)/256, 256>>>(out);
}

// round 12
// speedup vs baseline: 2.3054x; 1.7785x over previous
#include <cuda_runtime.h>
#include <math.h>
#include <stdint.h>

#define DIMC 1024
#define NHC  16
#define HDC  64
#define SEQ  2048
#define BATCH 2
#define NTOK 4096          // BATCH*SEQ
#define EXPN 8
#define TOPK 2
#define HIDC 1024
#define NROUTED (NTOK*TOPK)

// ---------------- scratch (static device globals; no allocation) -------------
__device__ float g_xn [NTOK*DIMC];
__device__ float g_q  [NTOK*DIMC];
__device__ float g_k  [NTOK*DIMC];
__device__ float g_v  [NTOK*DIMC];
__device__ float g_att[NTOK*DIMC];
__device__ float g_h  [NTOK*DIMC];
__device__ float g_hn [NTOK*DIMC];
__device__ float g_sh [NTOK*DIMC];
__device__ float g_e1 [NROUTED*HIDC];
__device__ float g_e3 [NROUTED*HIDC];
__device__ float g_eo [NROUTED*DIMC];
__device__ int   g_cnt [EXPN];
__device__ int   g_off [EXPN+1];
__device__ int   g_fill[EXPN];
__device__ int   g_tok_order[NROUTED];
__device__ int   g_tok_exp [NTOK*TOPK];
__device__ float g_tok_w   [NTOK*TOPK];
__device__ int   g_row_of  [NTOK*TOPK];

// ---------------- tf32 helpers -----------------------------------------------
__device__ __forceinline__ float f2tf32(float x) {
    uint32_t u;
    asm("cvt.rna.tf32.f32 %0, %1;" : "=r"(u) : "f"(x));
    return __uint_as_float(u);
}

__device__ __forceinline__ void mma_tf32(float c[4], const uint32_t a[4],
                                         const uint32_t b[2]) {
    asm volatile(
        "mma.sync.aligned.m16n8k8.row.col.f32.tf32.tf32.f32 "
        "{%0,%1,%2,%3},{%4,%5,%6,%7},{%8,%9},{%0,%1,%2,%3};"
        : "+f"(c[0]), "+f"(c[1]), "+f"(c[2]), "+f"(c[3])
        : "r"(a[0]), "r"(a[1]), "r"(a[2]), "r"(a[3]), "r"(b[0]), "r"(b[1]));
}

// smem strides (floats), conflict-free fragment access:
//   A: bank = (ASTR*r + c)%32 = (4r+c)%32 distinct (ASTR%32==4)
//   B: bank = (BSTR*k + n)%32 = (8k+n)%32 distinct (BSTR%32==8)
#define ASTR 36
#define BSTR 136
#define A_PLANE (128*ASTR)   // 4608 floats
#define B_PLANE (32*BSTR)    // 4352 floats

// ---------------- tensor-core GEMM: C[M,N] = A[M,K] * B[K,N] (+R) ------------
template <bool HIACC>
__global__ void __launch_bounds__(256) gemm_tc(
        const float* __restrict__ A, const float* __restrict__ B,
        float* __restrict__ C, const float* __restrict__ R,
        int M, int N, int K) {
    extern __shared__ float sm[];
    float* AsH = sm;
    float* BsH = sm + A_PLANE;
    float* AsL = HIACC ? sm + A_PLANE + B_PLANE : nullptr;
    float* BsL = HIACC ? sm + 2*A_PLANE + B_PLANE : nullptr;

    int tid  = threadIdx.x;
    int warp = tid >> 5, lane = tid & 31;
    int grp = lane >> 2, tig = lane & 3;
    int rowBase = (warp & 1) * 64;
    int colBase = (warp >> 1) * 32;
    int row0 = blockIdx.y * 128;
    int col0 = blockIdx.x * 128;

    int aRow = tid >> 1, aCol = (tid & 1) * 16;
    int bRow = tid >> 3, bCol = (tid & 7) * 16;
    const float* Ag = A + (size_t)(row0 + aRow) * K + aCol;
    const float* Bg = B + (size_t)bRow * N + col0 + bCol;

    float acc[4][4][4];
#pragma unroll
    for (int mt = 0; mt < 4; mt++)
#pragma unroll
        for (int nt = 0; nt < 4; nt++)
#pragma unroll
            for (int i = 0; i < 4; i++) acc[mt][nt][i] = 0.f;

    for (int k0 = 0; k0 < K; k0 += 32) {
#pragma unroll
        for (int i = 0; i < 4; i++) {
            float4 v = *(const float4*)(Ag + k0 + i*4);
            float4 h; h.x=f2tf32(v.x); h.y=f2tf32(v.y); h.z=f2tf32(v.z); h.w=f2tf32(v.w);
            *(float4*)&AsH[aRow*ASTR + aCol + i*4] = h;
            if (HIACC) {
                float4 l; l.x=f2tf32(v.x-h.x); l.y=f2tf32(v.y-h.y);
                l.z=f2tf32(v.z-h.z); l.w=f2tf32(v.w-h.w);
                *(float4*)&AsL[aRow*ASTR + aCol + i*4] = l;
            }
        }
#pragma unroll
        for (int i = 0; i < 4; i++) {
            float4 v = *(const float4*)(Bg + (size_t)k0 * N + i*4);
            float4 h; h.x=f2tf32(v.x); h.y=f2tf32(v.y); h.z=f2tf32(v.z); h.w=f2tf32(v.w);
            *(float4*)&BsH[bRow*BSTR + bCol + i*4] = h;
            if (HIACC) {
                float4 l; l.x=f2tf32(v.x-h.x); l.y=f2tf32(v.y-h.y);
                l.z=f2tf32(v.z-h.z); l.w=f2tf32(v.w-h.w);
                *(float4*)&BsL[bRow*BSTR + bCol + i*4] = l;
            }
        }
        __syncthreads();
#pragma unroll
        for (int kk = 0; kk < 32; kk += 8) {
            uint32_t aH[4][4], aL[4][4], bH[4][2], bL[4][2];
#pragma unroll
            for (int mt = 0; mt < 4; mt++) {
                int r0 = rowBase + mt*16 + grp;
                const float* p = &AsH[r0*ASTR + kk + tig];
                aH[mt][0] = __float_as_uint(p[0]);
                aH[mt][1] = __float_as_uint(p[8*ASTR]);
                aH[mt][2] = __float_as_uint(p[4]);
                aH[mt][3] = __float_as_uint(p[8*ASTR + 4]);
                if (HIACC) {
                    const float* q = &AsL[r0*ASTR + kk + tig];
                    aL[mt][0] = __float_as_uint(q[0]);
                    aL[mt][1] = __float_as_uint(q[8*ASTR]);
                    aL[mt][2] = __float_as_uint(q[4]);
                    aL[mt][3] = __float_as_uint(q[8*ASTR + 4]);
                }
            }
#pragma unroll
            for (int nt = 0; nt < 4; nt++) {
                int c = colBase + nt*8 + grp;
                const float* p = &BsH[(kk + tig)*BSTR + c];
                bH[nt][0] = __float_as_uint(p[0]);
                bH[nt][1] = __float_as_uint(p[4*BSTR]);
                if (HIACC) {
                    const float* q = &BsL[(kk + tig)*BSTR + c];
                    bL[nt][0] = __float_as_uint(q[0]);
                    bL[nt][1] = __float_as_uint(q[4*BSTR]);
                }
            }
#pragma unroll
            for (int nt = 0; nt < 4; nt++)
#pragma unroll
                for (int mt = 0; mt < 4; mt++) {
                    mma_tf32(acc[mt][nt], aH[mt], bH[nt]);
                    if (HIACC) {
                        mma_tf32(acc[mt][nt], aH[mt], bL[nt]);
                        mma_tf32(acc[mt][nt], aL[mt], bH[nt]);
                    }
                }
        }
        __syncthreads();
    }

#pragma unroll
    for (int mt = 0; mt < 4; mt++) {
        int r = row0 + rowBase + mt*16 + grp;
#pragma unroll
        for (int nt = 0; nt < 4; nt++) {
            int c = col0 + colBase + nt*8 + tig*2;
            size_t o0 = (size_t)r * N + c;
            size_t o1 = (size_t)(r + 8) * N + c;
            float2 v0 = make_float2(acc[mt][nt][0], acc[mt][nt][1]);
            float2 v1 = make_float2(acc[mt][nt][2], acc[mt][nt][3]);
            if (R) {
                v0.x += R[o0]; v0.y += R[o0+1];
                v1.x += R[o1]; v1.y += R[o1+1];
            }
            *(float2*)(C + o0) = v0;
            *(float2*)(C + o1) = v1;
        }
    }
}

// ---------------- grouped MoE tensor-core GEMM (single-pass TF32) ------------
__global__ void __launch_bounds__(256) gemm_tc_moe(
        const float* __restrict__ A, const float* __restrict__ Bbase,
        float* __restrict__ C, int useGather, int N, int K) {
    int e = blockIdx.z;
    int segBase = g_off[e];
    int segCnt  = g_off[e+1] - segBase;
    int rt = blockIdx.y * 128;
    if (rt >= segCnt) return;
    const float* B = Bbase + (size_t)e * K * N;

    extern __shared__ float sm[];
    float* AsH = sm;
    float* BsH = sm + A_PLANE;

    int tid  = threadIdx.x;
    int warp = tid >> 5, lane = tid & 31;
    int grp = lane >> 2, tig = lane & 3;
    int rowBase = (warp & 1) * 64;
    int colBase = (warp >> 1) * 32;
    int col0 = blockIdx.x * 128;

    int aRow = tid >> 1, aCol = (tid & 1) * 16;
    int bRow = tid >> 3, bCol = (tid & 7) * 16;
    int rl0 = rt + aRow;
    bool aValid = rl0 < segCnt;
    int arow_idx = 0;
    if (aValid) arow_idx = useGather ? g_tok_order[segBase + rl0] : (segBase + rl0);
    const float* Ag = A + (size_t)arow_idx * K + aCol;
    const float* Bg = B + (size_t)bRow * N + col0 + bCol;

    float acc[4][4][4];
#pragma unroll
    for (int mt = 0; mt < 4; mt++)
#pragma unroll
        for (int nt = 0; nt < 4; nt++)
#pragma unroll
            for (int i = 0; i < 4; i++) acc[mt][nt][i] = 0.f;

    for (int k0 = 0; k0 < K; k0 += 32) {
#pragma unroll
        for (int i = 0; i < 4; i++) {
            float4 v = aValid ? *(const float4*)(Ag + k0 + i*4)
                              : make_float4(0.f,0.f,0.f,0.f);
            float4 h; h.x=f2tf32(v.x); h.y=f2tf32(v.y); h.z=f2tf32(v.z); h.w=f2tf32(v.w);
            *(float4*)&AsH[aRow*ASTR + aCol + i*4] = h;
        }
#pragma unroll
        for (int i = 0; i < 4; i++) {
            float4 v = *(const float4*)(Bg + (size_t)k0 * N + i*4);
            float4 h; h.x=f2tf32(v.x); h.y=f2tf32(v.y); h.z=f2tf32(v.z); h.w=f2tf32(v.w);
            *(float4*)&BsH[bRow*BSTR + bCol + i*4] = h;
        }
        __syncthreads();
#pragma unroll
        for (int kk = 0; kk < 32; kk += 8) {
            uint32_t aH[4][4], bH[4][2];
#pragma unroll
            for (int mt = 0; mt < 4; mt++) {
                int r0 = rowBase + mt*16 + grp;
                const float* p = &AsH[r0*ASTR + kk + tig];
                aH[mt][0] = __float_as_uint(p[0]);
                aH[mt][1] = __float_as_uint(p[8*ASTR]);
                aH[mt][2] = __float_as_uint(p[4]);
                aH[mt][3] = __float_as_uint(p[8*ASTR + 4]);
            }
#pragma unroll
            for (int nt = 0; nt < 4; nt++) {
                int c = colBase + nt*8 + grp;
                const float* p = &BsH[(kk + tig)*BSTR + c];
                bH[nt][0] = __float_as_uint(p[0]);
                bH[nt][1] = __float_as_uint(p[4*BSTR]);
            }
#pragma unroll
            for (int nt = 0; nt < 4; nt++)
#pragma unroll
                for (int mt = 0; mt < 4; mt++)
                    mma_tf32(acc[mt][nt], aH[mt], bH[nt]);
        }
        __syncthreads();
    }

#pragma unroll
    for (int mt = 0; mt < 4; mt++) {
        int rl = rt + rowBase + mt*16 + grp;
#pragma unroll
        for (int nt = 0; nt < 4; nt++) {
            int c = col0 + colBase + nt*8 + tig*2;
            if (rl < segCnt) {
                size_t o = (size_t)(segBase + rl) * N + c;
                *(float2*)(C + o) = make_float2(acc[mt][nt][0], acc[mt][nt][1]);
            }
            if (rl + 8 < segCnt) {
                size_t o = (size_t)(segBase + rl + 8) * N + c;
                *(float2*)(C + o) = make_float2(acc[mt][nt][2], acc[mt][nt][3]);
            }
        }
    }
}

// ---------------- RMSNorm ----------------------------------------------------
__global__ void rmsnorm_kernel(const float* __restrict__ x,
                               const float* __restrict__ w,
                               float* __restrict__ y) {
    int row = blockIdx.x;
    const float* xr = x + (size_t)row * DIMC;
    int t = threadIdx.x;
    float v[4];
    float ss = 0.f;
#pragma unroll
    for (int i = 0; i < 4; i++) { v[i] = xr[t + 256*i]; ss += v[i]*v[i]; }
    __shared__ float red[8];
#pragma unroll
    for (int o = 16; o; o >>= 1) ss += __shfl_xor_sync(0xffffffffu, ss, o);
    if ((t & 31) == 0) red[t >> 5] = ss;
    __syncthreads();
    if (t < 8) {
        float s = red[t];
        s += __shfl_xor_sync(0xffu, s, 4);
        s += __shfl_xor_sync(0xffu, s, 2);
        s += __shfl_xor_sync(0xffu, s, 1);
        if (t == 0) red[0] = s;
    }
    __syncthreads();
    float scale = rsqrtf(red[0] * (1.0f/DIMC) + 1e-6f);
    float* yr = y + (size_t)row * DIMC;
#pragma unroll
    for (int i = 0; i < 4; i++) yr[t + 256*i] = v[i] * scale * w[t + 256*i];
}

// ---------------- RoPE (interleaved complex, applied to q and k) -------------
__global__ void rope_kernel(float* __restrict__ q, float* __restrict__ k,
                            const float* __restrict__ freqs) {
    int idx = blockIdx.x * blockDim.x + threadIdx.x;
    if (idx >= NTOK * NHC * (HDC/2)) return;
    int p = idx & 31;
    int h = (idx >> 5) & 15;
    int t = idx >> 9;
    int s = t & (SEQ - 1);
    float c  = freqs[(s * 32 + p) * 2 + 0];
    float sn = freqs[(s * 32 + p) * 2 + 1];
    size_t base = (size_t)t * DIMC + h * HDC + 2 * p;
    float a = q[base], b = q[base+1];
    q[base]   = a*c - b*sn;
    q[base+1] = a*sn + b*c;
    a = k[base]; b = k[base+1];
    k[base]   = a*c - b*sn;
    k[base+1] = a*sn + b*c;
}

// ---------------- tensor-core flash attention --------------------------------
// 64 q-rows/CTA, 64-wide KV tiles, 8 warps (4 m-tiles x 2 n-tiles).
// Scores and PV both 3xTF32 (routing-critical accuracy path).
#define QSTR 68     // %32==4 -> A-fragment conflict-free
#define KSTR 72     // %32==8 -> B-fragment conflict-free
#define QS_PLANE (64*QSTR)   // 4352
#define KT_PLANE (64*KSTR)   // 4608
#define SMEM_ATT ((2*QS_PLANE + 6*KT_PLANE + 128) * 4)

__global__ void __launch_bounds__(256) attn_tc(
        const float* __restrict__ Q, const float* __restrict__ Kp,
        const float* __restrict__ Vp, float* __restrict__ O) {
    extern __shared__ float sm[];
    float* QsH = sm;
    float* QsL = QsH + QS_PLANE;
    float* KtH = QsL + QS_PLANE;          // [d][j] (K transposed)
    float* KtL = KtH + KT_PLANE;
    float* VsH = KtL + KT_PLANE;          // [j][d]
    float* VsL = VsH + KT_PLANE;
    float* PsH = VsL + KT_PLANE;          // [q][j] : raw S, then p_hi
    float* PsL = PsH + KT_PLANE;          // p_lo
    float* sAlpha = PsL + KT_PLANE;       // [64]
    float* sLinv  = sAlpha + 64;          // [64]

    int bh = blockIdx.y;
    int b = bh >> 4;
    int h = bh & 15;
    int q0 = blockIdx.x * 64;
    const float* Qb = Q  + (size_t)b*SEQ*DIMC + h*HDC;
    const float* Kb = Kp + (size_t)b*SEQ*DIMC + h*HDC;
    const float* Vb = Vp + (size_t)b*SEQ*DIMC + h*HDC;

    int tid  = threadIdx.x;
    int warp = tid >> 5, lane = tid & 31;
    int grp = lane >> 2, tig = lane & 3;
    int mi = warp & 3, ni = warp >> 2;
    int mrow = mi * 16;
    int ncol = ni * 32;

    // stage Q (hi/lo)
    for (int i = tid; i < 64*64; i += 256) {
        int r = i >> 6, c = i & 63;
        float x = Qb[(size_t)(q0 + r) * DIMC + c];
        float hi = f2tf32(x);
        QsH[r*QSTR + c] = hi;
        QsL[r*QSTR + c] = f2tf32(x - hi);
    }
    __syncthreads();

    // preload Q fragments (A-operand) for all 8 k-steps
    uint32_t qH[8][4], qL[8][4];
#pragma unroll
    for (int ks = 0; ks < 8; ks++) {
        const float* p = &QsH[(mrow + grp)*QSTR + ks*8 + tig];
        qH[ks][0] = __float_as_uint(p[0]);
        qH[ks][1] = __float_as_uint(p[8*QSTR]);
        qH[ks][2] = __float_as_uint(p[4]);
        qH[ks][3] = __float_as_uint(p[8*QSTR + 4]);
        const float* q2 = &QsL[(mrow + grp)*QSTR + ks*8 + tig];
        qL[ks][0] = __float_as_uint(q2[0]);
        qL[ks][1] = __float_as_uint(q2[8*QSTR]);
        qL[ks][2] = __float_as_uint(q2[4]);
        qL[ks][3] = __float_as_uint(q2[8*QSTR + 4]);
    }

    float accO[4][4];
#pragma unroll
    for (int nt = 0; nt < 4; nt++)
#pragma unroll
        for (int i = 0; i < 4; i++) accO[nt][i] = 0.f;

    // softmax row state (per-thread row view: 4 threads per row, 16 cols each)
    int sr = tid >> 2, sc = (tid & 3) * 16;
    float m = -1e30f, l = 0.f;

    for (int kt = 0; kt < SEQ/64; kt++) {
        __syncthreads();   // previous PV done before overwriting K/V smem
        // stage K (transposed) and V, hi/lo
        for (int i = tid; i < 64*64; i += 256) {
            int j = i >> 6, d = i & 63;
            float kv = Kb[(size_t)(kt*64 + j) * DIMC + d];
            float hi = f2tf32(kv);
            KtH[d*KSTR + j] = hi;
            KtL[d*KSTR + j] = f2tf32(kv - hi);
            float vv = Vb[(size_t)(kt*64 + j) * DIMC + d];
            float h2 = f2tf32(vv);
            VsH[j*KSTR + d] = h2;
            VsL[j*KSTR + d] = f2tf32(vv - h2);
        }
        __syncthreads();

        // ---- scores S = Q @ K^T (3xTF32), Q frags in regs ----
        float accS[4][4];
#pragma unroll
        for (int nt = 0; nt < 4; nt++)
#pragma unroll
            for (int i = 0; i < 4; i++) accS[nt][i] = 0.f;
#pragma unroll
        for (int ks = 0; ks < 8; ks++) {
            uint32_t bH[4][2], bL[4][2];
#pragma unroll
            for (int nt = 0; nt < 4; nt++) {
                int c = ncol + nt*8 + grp;
                const float* p = &KtH[(ks*8 + tig)*KSTR + c];
                bH[nt][0] = __float_as_uint(p[0]);
                bH[nt][1] = __float_as_uint(p[4*KSTR]);
                const float* q2 = &KtL[(ks*8 + tig)*KSTR + c];
                bL[nt][0] = __float_as_uint(q2[0]);
                bL[nt][1] = __float_as_uint(q2[4*KSTR]);
            }
#pragma unroll
            for (int nt = 0; nt < 4; nt++) {
                mma_tf32(accS[nt], qH[ks], bH[nt]);
                mma_tf32(accS[nt], qH[ks], bL[nt]);
                mma_tf32(accS[nt], qL[ks], bH[nt]);
            }
        }
        // store scaled scores
#pragma unroll
        for (int nt = 0; nt < 4; nt++) {
            int c = ncol + nt*8 + 2*tig;
            *(float2*)&PsH[(mrow+grp)*KSTR + c] =
                make_float2(accS[nt][0]*0.125f, accS[nt][1]*0.125f);
            *(float2*)&PsH[(mrow+grp+8)*KSTR + c] =
                make_float2(accS[nt][2]*0.125f, accS[nt][3]*0.125f);
        }
        __syncthreads();

        // ---- online softmax over the 64-wide tile ----
        float sv[16];
#pragma unroll
        for (int i = 0; i < 16; i += 4)
            *(float4*)&sv[i] = *(const float4*)&PsH[sr*KSTR + sc + i];
        float tmax = sv[0];
#pragma unroll
        for (int i = 1; i < 16; i++) tmax = fmaxf(tmax, sv[i]);
        tmax = fmaxf(tmax, __shfl_xor_sync(0xffffffffu, tmax, 1));
        tmax = fmaxf(tmax, __shfl_xor_sync(0xffffffffu, tmax, 2));
        float mnew  = fmaxf(m, tmax);
        float alpha = __expf(m - mnew);
        float psum = 0.f;
        float ph[16], pl[16];
#pragma unroll
        for (int i = 0; i < 16; i++) {
            float p = __expf(sv[i] - mnew);
            psum += p;
            ph[i] = f2tf32(p);
            pl[i] = f2tf32(p - ph[i]);
        }
#pragma unroll
        for (int i = 0; i < 16; i += 4) {
            *(float4*)&PsH[sr*KSTR + sc + i] = *(float4*)&ph[i];
            *(float4*)&PsL[sr*KSTR + sc + i] = *(float4*)&pl[i];
        }
        psum += __shfl_xor_sync(0xffffffffu, psum, 1);
        psum += __shfl_xor_sync(0xffffffffu, psum, 2);
        l = l * alpha + psum;
        m = mnew;
        if ((tid & 3) == 0) sAlpha[sr] = alpha;
        __syncthreads();

        // ---- O = O*alpha + P @ V (3xTF32) ----
        float al0 = sAlpha[mrow + grp];
        float al1 = sAlpha[mrow + grp + 8];
#pragma unroll
        for (int nt = 0; nt < 4; nt++) {
            accO[nt][0] *= al0; accO[nt][1] *= al0;
            accO[nt][2] *= al1; accO[nt][3] *= al1;
        }
#pragma unroll
        for (int ks = 0; ks < 8; ks++) {
            uint32_t pHf[4], pLf[4], bH[4][2], bL[4][2];
            {
                const float* p = &PsH[(mrow + grp)*KSTR + ks*8 + tig];
                pHf[0] = __float_as_uint(p[0]);
                pHf[1] = __float_as_uint(p[8*KSTR]);
                pHf[2] = __float_as_uint(p[4]);
                pHf[3] = __float_as_uint(p[8*KSTR + 4]);
                const float* q2 = &PsL[(mrow + grp)*KSTR + ks*8 + tig];
                pLf[0] = __float_as_uint(q2[0]);
                pLf[1] = __float_as_uint(q2[8*KSTR]);
                pLf[2] = __float_as_uint(q2[4]);
                pLf[3] = __float_as_uint(q2[8*KSTR + 4]);
            }
#pragma unroll
            for (int nt = 0; nt < 4; nt++) {
                int c = ncol + nt*8 + grp;
                const float* p = &VsH[(ks*8 + tig)*KSTR + c];
                bH[nt][0] = __float_as_uint(p[0]);
                bH[nt][1] = __float_as_uint(p[4*KSTR]);
                const float* q2 = &VsL[(ks*8 + tig)*KSTR + c];
                bL[nt][0] = __float_as_uint(q2[0]);
                bL[nt][1] = __float_as_uint(q2[4*KSTR]);
            }
#pragma unroll
            for (int nt = 0; nt < 4; nt++) {
                mma_tf32(accO[nt], pHf, bH[nt]);
                mma_tf32(accO[nt], pHf, bL[nt]);
                mma_tf32(accO[nt], pLf, bH[nt]);
            }
        }
    }

    if ((tid & 3) == 0) sLinv[sr] = 1.f / l;
    __syncthreads();
    float li0 = sLinv[mrow + grp];
    float li1 = sLinv[mrow + grp + 8];
    float* Ob = O + (size_t)b*SEQ*DIMC + h*HDC;
#pragma unroll
    for (int nt = 0; nt < 4; nt++) {
        int c = ncol + nt*8 + 2*tig;
        size_t o0 = (size_t)(q0 + mrow + grp) * DIMC + c;
        size_t o1 = (size_t)(q0 + mrow + grp + 8) * DIMC + c;
        *(float2*)(Ob + o0) = make_float2(accO[nt][0]*li0, accO[nt][1]*li0);
        *(float2*)(Ob + o1) = make_float2(accO[nt][2]*li1, accO[nt][3]*li1);
    }
}

// ---------------- gating: softmax over 8, top-2 ------------------------------
__global__ void gate_kernel(const float* __restrict__ hn,
                            const float* __restrict__ gw) {
    int gt   = (blockIdx.x * blockDim.x + threadIdx.x) >> 5;
    int lane = threadIdx.x & 31;
    if (gt >= NTOK) return;
    const float* row = hn + (size_t)gt * DIMC;
    float vals[32];
#pragma unroll
    for (int i = 0; i < 32; i++) vals[i] = row[lane + 32*i];
    float logits[EXPN];
#pragma unroll
    for (int e = 0; e < EXPN; e++) {
        const float* we = gw + e * DIMC;
        float s = 0.f;
#pragma unroll
        for (int i = 0; i < 32; i++) s += vals[i] * we[lane + 32*i];
        s += __shfl_xor_sync(0xffffffffu, s, 16);
        s += __shfl_xor_sync(0xffffffffu, s, 8);
        s += __shfl_xor_sync(0xffffffffu, s, 4);
        s += __shfl_xor_sync(0xffffffffu, s, 2);
        s += __shfl_xor_sync(0xffffffffu, s, 1);
        logits[e] = s;
    }
    if (lane == 0) {
        float mx = logits[0];
#pragma unroll
        for (int e = 1; e < EXPN; e++) mx = fmaxf(mx, logits[e]);
        float p[EXPN], sum = 0.f;
#pragma unroll
        for (int e = 0; e < EXPN; e++) { p[e] = __expf(logits[e]-mx); sum += p[e]; }
        float inv = 1.f / sum;
#pragma unroll
        for (int e = 0; e < EXPN; e++) p[e] *= inv;
        int e0 = 0;
        for (int e = 1; e < EXPN; e++) if (p[e] > p[e0]) e0 = e;
        int e1 = (e0 == 0) ? 1 : 0;
        for (int e = 0; e < EXPN; e++) { if (e == e0) continue; if (p[e] > p[e1]) e1 = e; }
        g_tok_exp[gt*2+0] = e0;  g_tok_exp[gt*2+1] = e1;
        g_tok_w  [gt*2+0] = p[e0]; g_tok_w[gt*2+1] = p[e1];
        atomicAdd(&g_cnt[e0], 1);
        atomicAdd(&g_cnt[e1], 1);
    }
}

__global__ void zero_cnt_kernel() {
    if (threadIdx.x < EXPN) g_cnt[threadIdx.x] = 0;
}

__global__ void scan_kernel() {
    if (threadIdx.x == 0) {
        int o = 0;
        for (int e = 0; e < EXPN; e++) { g_off[e] = o; g_fill[e] = o; o += g_cnt[e]; }
        g_off[EXPN] = o;
    }
}

__global__ void scatter_kernel() {
    int t = blockIdx.x * blockDim.x + threadIdx.x;
    if (t >= NTOK) return;
#pragma unroll
    for (int k = 0; k < TOPK; k++) {
        int e = g_tok_exp[t*2+k];
        int slot = atomicAdd(&g_fill[e], 1);
        g_tok_order[slot] = t;
        g_row_of[t*2+k] = slot;
    }
}

// ---------------- elementwise silu(a)*b (in place into a) --------------------
__global__ void silumul_kernel(float* __restrict__ a, const float* __restrict__ b,
                               int n) {
    int i = blockIdx.x * blockDim.x + threadIdx.x;
    if (i < n) {
        float x = a[i];
        a[i] = (x / (1.f + __expf(-x))) * b[i];
    }
}

// ---------------- final combine ----------------------------------------------
__global__ void combine_kernel(float* __restrict__ out) {
    int i = blockIdx.x * blockDim.x + threadIdx.x;
    if (i >= NTOK*DIMC) return;
    int t = i >> 10, d = i & 1023;
    int s0 = g_row_of[t*2+0], s1 = g_row_of[t*2+1];
    float w0 = g_tok_w[t*2+0], w1 = g_tok_w[t*2+1];
    float y = w0 * g_eo[(size_t)s0*DIMC + d] + w1 * g_eo[(size_t)s1*DIMC + d];
    out[i] = g_h[i] + g_sh[i] + y;
}

// ---------------- host orchestration -----------------------------------------
#define SMEM_HI ((2*A_PLANE + 2*B_PLANE) * 4)   // 71680 B
#define SMEM_LO ((A_PLANE + B_PLANE) * 4)       // 35840 B

extern "C" void kernel_launch(void* const* d_in, const int* in_sizes, int n_in,
                              void* d_out, int out_size) {
    const float* x    = (const float*)d_in[0];
    const float* freqs= (const float*)d_in[1];
    const float* anw  = (const float*)d_in[2];
    const float* wq   = (const float*)d_in[3];
    const float* wk   = (const float*)d_in[4];
    const float* wv   = (const float*)d_in[5];
    const float* wo   = (const float*)d_in[6];
    const float* fnw  = (const float*)d_in[7];
    const float* gw   = (const float*)d_in[8];
    const float* ew1  = (const float*)d_in[9];
    const float* ew2  = (const float*)d_in[10];
    const float* ew3  = (const float*)d_in[11];
    const float* sw1  = (const float*)d_in[12];
    const float* sw2  = (const float*)d_in[13];
    const float* sw3  = (const float*)d_in[14];
    float* out = (float*)d_out;

    float *xn, *q, *k, *v, *att, *h, *hn, *sh, *e1, *e3, *eo;
    cudaGetSymbolAddress((void**)&xn,  g_xn);
    cudaGetSymbolAddress((void**)&q,   g_q);
    cudaGetSymbolAddress((void**)&k,   g_k);
    cudaGetSymbolAddress((void**)&v,   g_v);
    cudaGetSymbolAddress((void**)&att, g_att);
    cudaGetSymbolAddress((void**)&h,   g_h);
    cudaGetSymbolAddress((void**)&hn,  g_hn);
    cudaGetSymbolAddress((void**)&sh,  g_sh);
    cudaGetSymbolAddress((void**)&e1,  g_e1);
    cudaGetSymbolAddress((void**)&e3,  g_e3);
    cudaGetSymbolAddress((void**)&eo,  g_eo);

    // stateless: set every call (idempotent, host-side, capture-legal)
    cudaFuncSetAttribute(gemm_tc<true>,
        cudaFuncAttributeMaxDynamicSharedMemorySize, SMEM_HI);
    cudaFuncSetAttribute(gemm_tc<false>,
        cudaFuncAttributeMaxDynamicSharedMemorySize, SMEM_LO);
    cudaFuncSetAttribute(gemm_tc_moe,
        cudaFuncAttributeMaxDynamicSharedMemorySize, SMEM_LO);
    cudaFuncSetAttribute(attn_tc,
        cudaFuncAttributeMaxDynamicSharedMemorySize, SMEM_ATT);

    dim3 gGemm(DIMC/128, NTOK/128);   // (8, 32)

    // attention sub-block (3xTF32: routing-critical accuracy)
    rmsnorm_kernel<<<NTOK, 256>>>(x, anw, xn);
    gemm_tc<true><<<gGemm, 256, SMEM_HI>>>(xn, wq, q, nullptr, NTOK, DIMC, DIMC);
    gemm_tc<true><<<gGemm, 256, SMEM_HI>>>(xn, wk, k, nullptr, NTOK, DIMC, DIMC);
    gemm_tc<true><<<gGemm, 256, SMEM_HI>>>(xn, wv, v, nullptr, NTOK, DIMC, DIMC);
    rope_kernel<<<(NTOK*NHC*32 + 255)/256, 256>>>(q, k, freqs);
    attn_tc<<<dim3(SEQ/64, BATCH*NHC), 256, SMEM_ATT>>>(q, k, v, att);
    gemm_tc<true><<<gGemm, 256, SMEM_HI>>>(att, wo, h, x, NTOK, DIMC, DIMC);

    // MoE sub-block
    rmsnorm_kernel<<<NTOK, 256>>>(h, fnw, hn);
    zero_cnt_kernel<<<1, 32>>>();
    gate_kernel<<<NTOK/8, 256>>>(hn, gw);
    scan_kernel<<<1, 32>>>();
    scatter_kernel<<<NTOK/256, 256>>>();

    dim3 gMoe1(HIDC/128, NROUTED/128, EXPN);
    gemm_tc_moe<<<gMoe1, 256, SMEM_LO>>>(hn, ew1, e1, 1, HIDC, DIMC);
    gemm_tc_moe<<<gMoe1, 256, SMEM_LO>>>(hn, ew3, e3, 1, HIDC, DIMC);
    silumul_kernel<<<(NROUTED*HIDC)/256, 256>>>(e1, e3, NROUTED*HIDC);
    dim3 gMoe2(DIMC/128, NROUTED/128, EXPN);
    gemm_tc_moe<<<gMoe2, 256, SMEM_LO>>>(e1, ew2, eo, 0, DIMC, HIDC);

    // shared expert (single-pass TF32; output-only path)
    gemm_tc<false><<<gGemm, 256, SMEM_LO>>>(hn, sw1, q, nullptr, NTOK, DIMC, DIMC);
    gemm_tc<false><<<gGemm, 256, SMEM_LO>>>(hn, sw3, k, nullptr, NTOK, DIMC, DIMC);
    silumul_kernel<<<(NTOK*DIMC)/256, 256>>>(q, k, NTOK*DIMC);
    gemm_tc<false><<<gGemm, 256, SMEM_LO>>>(q, sw2, sh, nullptr, NTOK, DIMC, DIMC);

    combine_kernel<<<(NTOK*DIMC)/256, 256>>>(out);
}

// round 14
// speedup vs baseline: 2.3414x; 1.0156x over previous
#include <cuda_runtime.h>
#include <math.h>
#include <stdint.h>

#define DIMC 1024
#define NHC  16
#define HDC  64
#define SEQ  2048
#define BATCH 2
#define NTOK 4096          // BATCH*SEQ
#define EXPN 8
#define TOPK 2
#define HIDC 1024
#define NROUTED (NTOK*TOPK)

// ---------------- scratch (static device globals; no allocation) -------------
__device__ float g_xn [NTOK*DIMC];
__device__ float g_q  [NTOK*DIMC];
__device__ float g_k  [NTOK*DIMC];
__device__ float g_v  [NTOK*DIMC];
__device__ float g_att[NTOK*DIMC];
__device__ float g_h  [NTOK*DIMC];
__device__ float g_hn [NTOK*DIMC];
__device__ float g_sh [NTOK*DIMC];
__device__ float g_e1 [NROUTED*HIDC];
__device__ float g_e3 [NROUTED*HIDC];
__device__ float g_eo [NROUTED*DIMC];
__device__ int   g_cnt [EXPN];
__device__ int   g_off [EXPN+1];
__device__ int   g_fill[EXPN];
__device__ int   g_tok_order[NROUTED];
__device__ int   g_tok_exp [NTOK*TOPK];
__device__ float g_tok_w   [NTOK*TOPK];
__device__ int   g_row_of  [NTOK*TOPK];

// ---------------- tf32 / cp.async helpers ------------------------------------
__device__ __forceinline__ float f2tf32(float x) {
    uint32_t u;
    asm("cvt.rna.tf32.f32 %0, %1;" : "=r"(u) : "f"(x));
    return __uint_as_float(u);
}

__device__ __forceinline__ void mma_tf32(float c[4], const uint32_t a[4],
                                         const uint32_t b[2]) {
    asm volatile(
        "mma.sync.aligned.m16n8k8.row.col.f32.tf32.tf32.f32 "
        "{%0,%1,%2,%3},{%4,%5,%6,%7},{%8,%9},{%0,%1,%2,%3};"
        : "+f"(c[0]), "+f"(c[1]), "+f"(c[2]), "+f"(c[3])
        : "r"(a[0]), "r"(a[1]), "r"(a[2]), "r"(a[3]), "r"(b[0]), "r"(b[1]));
}

__device__ __forceinline__ void cp_async16(float* dst, const float* src, bool valid) {
    uint32_t d = (uint32_t)__cvta_generic_to_shared(dst);
    int sz = valid ? 16 : 0;
    asm volatile("cp.async.cg.shared.global [%0], [%1], 16, %2;\n"
                 :: "r"(d), "l"(src), "r"(sz));
}
__device__ __forceinline__ void cp_commit() {
    asm volatile("cp.async.commit_group;\n" ::: "memory");
}
__device__ __forceinline__ void cp_wait1() {
    asm volatile("cp.async.wait_group 1;\n" ::: "memory");
}
__device__ __forceinline__ void cp_wait0() {
    asm volatile("cp.async.wait_group 0;\n" ::: "memory");
}

// smem strides (floats), conflict-free fragment access:
//   A: bank = (ASTR*r + c)%32 = (4r+c)%32 distinct (ASTR%32==4)
//   B: bank = (BSTR*k + n)%32 = (8k+n)%32 distinct (BSTR%32==8)
// 16B alignment for cp.async: 36*4=144B ✓, 136*4=544B ✓
#define ASTR 36
#define BSTR 136
#define A_PLANE (128*ASTR)           // 4608 floats
#define B_PLANE (32*BSTR)            // 4352 floats
#define STAGE   (A_PLANE + B_PLANE)  // 8960 floats per buffer
#define SMEM_GM (2*STAGE*4)          // 71680 B (double-buffered raw fp32)

// ---------------- tensor-core GEMM: C[M,N] = A[M,K] * B[K,N] (+R) ------------
// Raw fp32 staged via cp.async double buffer; tf32 hi/lo split at fragment load.
template <bool HIACC>
__global__ void __launch_bounds__(256, 2) gemm_tc(
        const float* __restrict__ A, const float* __restrict__ B,
        float* __restrict__ C, const float* __restrict__ R,
        int M, int N, int K) {
    extern __shared__ float sm[];

    int tid  = threadIdx.x;
    int warp = tid >> 5, lane = tid & 31;
    int grp = lane >> 2, tig = lane & 3;
    int rowBase = (warp & 1) * 64;
    int colBase = (warp >> 1) * 32;
    int row0 = blockIdx.y * 128;
    int col0 = blockIdx.x * 128;

    int aRow = tid >> 1, aCol = (tid & 1) * 16;
    int bRow = tid >> 3, bCol = (tid & 7) * 16;
    const float* Ag = A + (size_t)(row0 + aRow) * K + aCol;
    const float* Bg = B + (size_t)bRow * N + col0 + bCol;

    float acc[4][4][4];
#pragma unroll
    for (int mt = 0; mt < 4; mt++)
#pragma unroll
        for (int nt = 0; nt < 4; nt++)
#pragma unroll
            for (int i = 0; i < 4; i++) acc[mt][nt][i] = 0.f;

    // stage tile k0 into buffer buf
    auto stage = [&](int k0, int buf) {
        float* Ad = sm + buf*STAGE + aRow*ASTR + aCol;
        const float* As = Ag + k0;
#pragma unroll
        for (int i = 0; i < 4; i++) cp_async16(Ad + i*4, As + i*4, true);
        float* Bd = sm + buf*STAGE + A_PLANE + bRow*BSTR + bCol;
        const float* Bs = Bg + (size_t)k0 * N;
#pragma unroll
        for (int i = 0; i < 4; i++) cp_async16(Bd + i*4, Bs + i*4, true);
        cp_commit();
    };

    stage(0, 0);
    for (int k0 = 0; k0 < K; k0 += 32) {
        int buf = (k0 >> 5) & 1;
        bool hasNext = (k0 + 32) < K;
        if (hasNext) stage(k0 + 32, buf ^ 1);
        if (hasNext) cp_wait1(); else cp_wait0();
        __syncthreads();
        const float* AsB = sm + buf*STAGE;
        const float* BsB = AsB + A_PLANE;
#pragma unroll
        for (int kk = 0; kk < 32; kk += 8) {
            uint32_t aH[4][4], aL[4][4], bH[4][2], bL[4][2];
#pragma unroll
            for (int mt = 0; mt < 4; mt++) {
                const float* p = &AsB[(rowBase + mt*16 + grp)*ASTR + kk + tig];
                float x0 = p[0], x1 = p[8*ASTR], x2 = p[4], x3 = p[8*ASTR + 4];
                float h0 = f2tf32(x0), h1 = f2tf32(x1), h2 = f2tf32(x2), h3 = f2tf32(x3);
                aH[mt][0] = __float_as_uint(h0);
                aH[mt][1] = __float_as_uint(h1);
                aH[mt][2] = __float_as_uint(h2);
                aH[mt][3] = __float_as_uint(h3);
                if (HIACC) {
                    aL[mt][0] = __float_as_uint(f2tf32(x0 - h0));
                    aL[mt][1] = __float_as_uint(f2tf32(x1 - h1));
                    aL[mt][2] = __float_as_uint(f2tf32(x2 - h2));
                    aL[mt][3] = __float_as_uint(f2tf32(x3 - h3));
                }
            }
#pragma unroll
            for (int nt = 0; nt < 4; nt++) {
                const float* p = &BsB[(kk + tig)*BSTR + colBase + nt*8 + grp];
                float x0 = p[0], x1 = p[4*BSTR];
                float h0 = f2tf32(x0), h1 = f2tf32(x1);
                bH[nt][0] = __float_as_uint(h0);
                bH[nt][1] = __float_as_uint(h1);
                if (HIACC) {
                    bL[nt][0] = __float_as_uint(f2tf32(x0 - h0));
                    bL[nt][1] = __float_as_uint(f2tf32(x1 - h1));
                }
            }
#pragma unroll
            for (int nt = 0; nt < 4; nt++)
#pragma unroll
                for (int mt = 0; mt < 4; mt++) {
                    mma_tf32(acc[mt][nt], aH[mt], bH[nt]);
                    if (HIACC) {
                        mma_tf32(acc[mt][nt], aH[mt], bL[nt]);
                        mma_tf32(acc[mt][nt], aL[mt], bH[nt]);
                    }
                }
        }
        __syncthreads();
    }

#pragma unroll
    for (int mt = 0; mt < 4; mt++) {
        int r = row0 + rowBase + mt*16 + grp;
#pragma unroll
        for (int nt = 0; nt < 4; nt++) {
            int c = col0 + colBase + nt*8 + tig*2;
            size_t o0 = (size_t)r * N + c;
            size_t o1 = (size_t)(r + 8) * N + c;
            float2 v0 = make_float2(acc[mt][nt][0], acc[mt][nt][1]);
            float2 v1 = make_float2(acc[mt][nt][2], acc[mt][nt][3]);
            if (R) {
                v0.x += R[o0]; v0.y += R[o0+1];
                v1.x += R[o1]; v1.y += R[o1+1];
            }
            *(float2*)(C + o0) = v0;
            *(float2*)(C + o1) = v1;
        }
    }
}

// ---------------- grouped MoE tensor-core GEMM (single-pass TF32) ------------
__global__ void __launch_bounds__(256, 2) gemm_tc_moe(
        const float* __restrict__ A, const float* __restrict__ Bbase,
        float* __restrict__ C, int useGather, int N, int K) {
    int e = blockIdx.z;
    int segBase = g_off[e];
    int segCnt  = g_off[e+1] - segBase;
    int rt = blockIdx.y * 128;
    if (rt >= segCnt) return;
    const float* B = Bbase + (size_t)e * K * N;

    extern __shared__ float sm[];

    int tid  = threadIdx.x;
    int warp = tid >> 5, lane = tid & 31;
    int grp = lane >> 2, tig = lane & 3;
    int rowBase = (warp & 1) * 64;
    int colBase = (warp >> 1) * 32;
    int col0 = blockIdx.x * 128;

    int aRow = tid >> 1, aCol = (tid & 1) * 16;
    int bRow = tid >> 3, bCol = (tid & 7) * 16;
    int rl0 = rt + aRow;
    bool aValid = rl0 < segCnt;
    int arow_idx = 0;
    if (aValid) arow_idx = useGather ? g_tok_order[segBase + rl0] : (segBase + rl0);
    const float* Ag = A + (size_t)arow_idx * K + aCol;
    const float* Bg = B + (size_t)bRow * N + col0 + bCol;

    float acc[4][4][4];
#pragma unroll
    for (int mt = 0; mt < 4; mt++)
#pragma unroll
        for (int nt = 0; nt < 4; nt++)
#pragma unroll
            for (int i = 0; i < 4; i++) acc[mt][nt][i] = 0.f;

    auto stage = [&](int k0, int buf) {
        float* Ad = sm + buf*STAGE + aRow*ASTR + aCol;
        const float* As = Ag + k0;
#pragma unroll
        for (int i = 0; i < 4; i++) cp_async16(Ad + i*4, As + i*4, aValid);
        float* Bd = sm + buf*STAGE + A_PLANE + bRow*BSTR + bCol;
        const float* Bs = Bg + (size_t)k0 * N;
#pragma unroll
        for (int i = 0; i < 4; i++) cp_async16(Bd + i*4, Bs + i*4, true);
        cp_commit();
    };

    stage(0, 0);
    for (int k0 = 0; k0 < K; k0 += 32) {
        int buf = (k0 >> 5) & 1;
        bool hasNext = (k0 + 32) < K;
        if (hasNext) stage(k0 + 32, buf ^ 1);
        if (hasNext) cp_wait1(); else cp_wait0();
        __syncthreads();
        const float* AsB = sm + buf*STAGE;
        const float* BsB = AsB + A_PLANE;
#pragma unroll
        for (int kk = 0; kk < 32; kk += 8) {
            uint32_t aH[4][4], bH[4][2];
#pragma unroll
            for (int mt = 0; mt < 4; mt++) {
                const float* p = &AsB[(rowBase + mt*16 + grp)*ASTR + kk + tig];
                aH[mt][0] = __float_as_uint(f2tf32(p[0]));
                aH[mt][1] = __float_as_uint(f2tf32(p[8*ASTR]));
                aH[mt][2] = __float_as_uint(f2tf32(p[4]));
                aH[mt][3] = __float_as_uint(f2tf32(p[8*ASTR + 4]));
            }
#pragma unroll
            for (int nt = 0; nt < 4; nt++) {
                const float* p = &BsB[(kk + tig)*BSTR + colBase + nt*8 + grp];
                bH[nt][0] = __float_as_uint(f2tf32(p[0]));
                bH[nt][1] = __float_as_uint(f2tf32(p[4*BSTR]));
            }
#pragma unroll
            for (int nt = 0; nt < 4; nt++)
#pragma unroll
                for (int mt = 0; mt < 4; mt++)
                    mma_tf32(acc[mt][nt], aH[mt], bH[nt]);
        }
        __syncthreads();
    }

#pragma unroll
    for (int mt = 0; mt < 4; mt++) {
        int rl = rt + rowBase + mt*16 + grp;
#pragma unroll
        for (int nt = 0; nt < 4; nt++) {
            int c = col0 + colBase + nt*8 + tig*2;
            if (rl < segCnt) {
                size_t o = (size_t)(segBase + rl) * N + c;
                *(float2*)(C + o) = make_float2(acc[mt][nt][0], acc[mt][nt][1]);
            }
            if (rl + 8 < segCnt) {
                size_t o = (size_t)(segBase + rl + 8) * N + c;
                *(float2*)(C + o) = make_float2(acc[mt][nt][2], acc[mt][nt][3]);
            }
        }
    }
}

// ---------------- RMSNorm ----------------------------------------------------
__global__ void rmsnorm_kernel(const float* __restrict__ x,
                               const float* __restrict__ w,
                               float* __restrict__ y) {
    int row = blockIdx.x;
    const float* xr = x + (size_t)row * DIMC;
    int t = threadIdx.x;
    float v[4];
    float ss = 0.f;
#pragma unroll
    for (int i = 0; i < 4; i++) { v[i] = xr[t + 256*i]; ss += v[i]*v[i]; }
    __shared__ float red[8];
#pragma unroll
    for (int o = 16; o; o >>= 1) ss += __shfl_xor_sync(0xffffffffu, ss, o);
    if ((t & 31) == 0) red[t >> 5] = ss;
    __syncthreads();
    if (t < 8) {
        float s = red[t];
        s += __shfl_xor_sync(0xffu, s, 4);
        s += __shfl_xor_sync(0xffu, s, 2);
        s += __shfl_xor_sync(0xffu, s, 1);
        if (t == 0) red[0] = s;
    }
    __syncthreads();
    float scale = rsqrtf(red[0] * (1.0f/DIMC) + 1e-6f);
    float* yr = y + (size_t)row * DIMC;
#pragma unroll
    for (int i = 0; i < 4; i++) yr[t + 256*i] = v[i] * scale * w[t + 256*i];
}

// ---------------- RoPE (interleaved complex, applied to q and k) -------------
__global__ void rope_kernel(float* __restrict__ q, float* __restrict__ k,
                            const float* __restrict__ freqs) {
    int idx = blockIdx.x * blockDim.x + threadIdx.x;
    if (idx >= NTOK * NHC * (HDC/2)) return;
    int p = idx & 31;
    int h = (idx >> 5) & 15;
    int t = idx >> 9;
    int s = t & (SEQ - 1);
    float c  = freqs[(s * 32 + p) * 2 + 0];
    float sn = freqs[(s * 32 + p) * 2 + 1];
    size_t base = (size_t)t * DIMC + h * HDC + 2 * p;
    float a = q[base], b = q[base+1];
    q[base]   = a*c - b*sn;
    q[base+1] = a*sn + b*c;
    a = k[base]; b = k[base+1];
    k[base]   = a*c - b*sn;
    k[base+1] = a*sn + b*c;
}

// ---------------- tensor-core flash attention --------------------------------
// 64 q-rows/CTA, 64-wide KV tiles, 8 warps (4 m-tiles x 2 n-tiles).
// Scores and PV both 3xTF32 (routing-critical accuracy path).
#define QSTR 68     // %32==4 -> A-fragment conflict-free
#define KSTR 72     // %32==8 -> B-fragment conflict-free
#define QS_PLANE (64*QSTR)   // 4352
#define KT_PLANE (64*KSTR)   // 4608
#define SMEM_ATT ((2*QS_PLANE + 6*KT_PLANE + 128) * 4)

__global__ void __launch_bounds__(256) attn_tc(
        const float* __restrict__ Q, const float* __restrict__ Kp,
        const float* __restrict__ Vp, float* __restrict__ O) {
    extern __shared__ float sm[];
    float* QsH = sm;
    float* QsL = QsH + QS_PLANE;
    float* KtH = QsL + QS_PLANE;          // [d][j] (K transposed)
    float* KtL = KtH + KT_PLANE;
    float* VsH = KtL + KT_PLANE;          // [j][d]
    float* VsL = VsH + KT_PLANE;
    float* PsH = VsL + KT_PLANE;          // [q][j] : raw S, then p_hi
    float* PsL = PsH + KT_PLANE;          // p_lo
    float* sAlpha = PsL + KT_PLANE;       // [64]
    float* sLinv  = sAlpha + 64;          // [64]

    int bh = blockIdx.y;
    int b = bh >> 4;
    int h = bh & 15;
    int q0 = blockIdx.x * 64;
    const float* Qb = Q  + (size_t)b*SEQ*DIMC + h*HDC;
    const float* Kb = Kp + (size_t)b*SEQ*DIMC + h*HDC;
    const float* Vb = Vp + (size_t)b*SEQ*DIMC + h*HDC;

    int tid  = threadIdx.x;
    int warp = tid >> 5, lane = tid & 31;
    int grp = lane >> 2, tig = lane & 3;
    int mi = warp & 3, ni = warp >> 2;
    int mrow = mi * 16;
    int ncol = ni * 32;

    // stage Q (hi/lo)
    for (int i = tid; i < 64*64; i += 256) {
        int r = i >> 6, c = i & 63;
        float x = Qb[(size_t)(q0 + r) * DIMC + c];
        float hi = f2tf32(x);
        QsH[r*QSTR + c] = hi;
        QsL[r*QSTR + c] = f2tf32(x - hi);
    }
    __syncthreads();

    // preload Q fragments (A-operand) for all 8 k-steps
    uint32_t qH[8][4], qL[8][4];
#pragma unroll
    for (int ks = 0; ks < 8; ks++) {
        const float* p = &QsH[(mrow + grp)*QSTR + ks*8 + tig];
        qH[ks][0] = __float_as_uint(p[0]);
        qH[ks][1] = __float_as_uint(p[8*QSTR]);
        qH[ks][2] = __float_as_uint(p[4]);
        qH[ks][3] = __float_as_uint(p[8*QSTR + 4]);
        const float* q2 = &QsL[(mrow + grp)*QSTR + ks*8 + tig];
        qL[ks][0] = __float_as_uint(q2[0]);
        qL[ks][1] = __float_as_uint(q2[8*QSTR]);
        qL[ks][2] = __float_as_uint(q2[4]);
        qL[ks][3] = __float_as_uint(q2[8*QSTR + 4]);
    }

    float accO[4][4];
#pragma unroll
    for (int nt = 0; nt < 4; nt++)
#pragma unroll
        for (int i = 0; i < 4; i++) accO[nt][i] = 0.f;

    // softmax row state (per-thread row view: 4 threads per row, 16 cols each)
    int sr = tid >> 2, sc = (tid & 3) * 16;
    float m = -1e30f, l = 0.f;

    for (int kt = 0; kt < SEQ/64; kt++) {
        __syncthreads();   // previous PV done before overwriting K/V smem
        // stage K (transposed) and V, hi/lo
        for (int i = tid; i < 64*64; i += 256) {
            int j = i >> 6, d = i & 63;
            float kv = Kb[(size_t)(kt*64 + j) * DIMC + d];
            float hi = f2tf32(kv);
            KtH[d*KSTR + j] = hi;
            KtL[d*KSTR + j] = f2tf32(kv - hi);
            float vv = Vb[(size_t)(kt*64 + j) * DIMC + d];
            float h2 = f2tf32(vv);
            VsH[j*KSTR + d] = h2;
            VsL[j*KSTR + d] = f2tf32(vv - h2);
        }
        __syncthreads();

        // ---- scores S = Q @ K^T (3xTF32), Q frags in regs ----
        float accS[4][4];
#pragma unroll
        for (int nt = 0; nt < 4; nt++)
#pragma unroll
            for (int i = 0; i < 4; i++) accS[nt][i] = 0.f;
#pragma unroll
        for (int ks = 0; ks < 8; ks++) {
            uint32_t bH[4][2], bL[4][2];
#pragma unroll
            for (int nt = 0; nt < 4; nt++) {
                int c = ncol + nt*8 + grp;
                const float* p = &KtH[(ks*8 + tig)*KSTR + c];
                bH[nt][0] = __float_as_uint(p[0]);
                bH[nt][1] = __float_as_uint(p[4*KSTR]);
                const float* q2 = &KtL[(ks*8 + tig)*KSTR + c];
                bL[nt][0] = __float_as_uint(q2[0]);
                bL[nt][1] = __float_as_uint(q2[4*KSTR]);
            }
#pragma unroll
            for (int nt = 0; nt < 4; nt++) {
                mma_tf32(accS[nt], qH[ks], bH[nt]);
                mma_tf32(accS[nt], qH[ks], bL[nt]);
                mma_tf32(accS[nt], qL[ks], bH[nt]);
            }
        }
        // store scaled scores
#pragma unroll
        for (int nt = 0; nt < 4; nt++) {
            int c = ncol + nt*8 + 2*tig;
            *(float2*)&PsH[(mrow+grp)*KSTR + c] =
                make_float2(accS[nt][0]*0.125f, accS[nt][1]*0.125f);
            *(float2*)&PsH[(mrow+grp+8)*KSTR + c] =
                make_float2(accS[nt][2]*0.125f, accS[nt][3]*0.125f);
        }
        __syncthreads();

        // ---- online softmax over the 64-wide tile ----
        float sv[16];
#pragma unroll
        for (int i = 0; i < 16; i += 4)
            *(float4*)&sv[i] = *(const float4*)&PsH[sr*KSTR + sc + i];
        float tmax = sv[0];
#pragma unroll
        for (int i = 1; i < 16; i++) tmax = fmaxf(tmax, sv[i]);
        tmax = fmaxf(tmax, __shfl_xor_sync(0xffffffffu, tmax, 1));
        tmax = fmaxf(tmax, __shfl_xor_sync(0xffffffffu, tmax, 2));
        float mnew  = fmaxf(m, tmax);
        float alpha = __expf(m - mnew);
        float psum = 0.f;
        float ph[16], pl[16];
#pragma unroll
        for (int i = 0; i < 16; i++) {
            float p = __expf(sv[i] - mnew);
            psum += p;
            ph[i] = f2tf32(p);
            pl[i] = f2tf32(p - ph[i]);
        }
#pragma unroll
        for (int i = 0; i < 16; i += 4) {
            *(float4*)&PsH[sr*KSTR + sc + i] = *(float4*)&ph[i];
            *(float4*)&PsL[sr*KSTR + sc + i] = *(float4*)&pl[i];
        }
        psum += __shfl_xor_sync(0xffffffffu, psum, 1);
        psum += __shfl_xor_sync(0xffffffffu, psum, 2);
        l = l * alpha + psum;
        m = mnew;
        if ((tid & 3) == 0) sAlpha[sr] = alpha;
        __syncthreads();

        // ---- O = O*alpha + P @ V (3xTF32) ----
        float al0 = sAlpha[mrow + grp];
        float al1 = sAlpha[mrow + grp + 8];
#pragma unroll
        for (int nt = 0; nt < 4; nt++) {
            accO[nt][0] *= al0; accO[nt][1] *= al0;
            accO[nt][2] *= al1; accO[nt][3] *= al1;
        }
#pragma unroll
        for (int ks = 0; ks < 8; ks++) {
            uint32_t pHf[4], pLf[4], bH[4][2], bL[4][2];
            {
                const float* p = &PsH[(mrow + grp)*KSTR + ks*8 + tig];
                pHf[0] = __float_as_uint(p[0]);
                pHf[1] = __float_as_uint(p[8*KSTR]);
                pHf[2] = __float_as_uint(p[4]);
                pHf[3] = __float_as_uint(p[8*KSTR + 4]);
                const float* q2 = &PsL[(mrow + grp)*KSTR + ks*8 + tig];
                pLf[0] = __float_as_uint(q2[0]);
                pLf[1] = __float_as_uint(q2[8*KSTR]);
                pLf[2] = __float_as_uint(q2[4]);
                pLf[3] = __float_as_uint(q2[8*KSTR + 4]);
            }
#pragma unroll
            for (int nt = 0; nt < 4; nt++) {
                int c = ncol + nt*8 + grp;
                const float* p = &VsH[(ks*8 + tig)*KSTR + c];
                bH[nt][0] = __float_as_uint(p[0]);
                bH[nt][1] = __float_as_uint(p[4*KSTR]);
                const float* q2 = &VsL[(ks*8 + tig)*KSTR + c];
                bL[nt][0] = __float_as_uint(q2[0]);
                bL[nt][1] = __float_as_uint(q2[4*KSTR]);
            }
#pragma unroll
            for (int nt = 0; nt < 4; nt++) {
                mma_tf32(accO[nt], pHf, bH[nt]);
                mma_tf32(accO[nt], pHf, bL[nt]);
                mma_tf32(accO[nt], pLf, bH[nt]);
            }
        }
    }

    if ((tid & 3) == 0) sLinv[sr] = 1.f / l;
    __syncthreads();
    float li0 = sLinv[mrow + grp];
    float li1 = sLinv[mrow + grp + 8];
    float* Ob = O + (size_t)b*SEQ*DIMC + h*HDC;
#pragma unroll
    for (int nt = 0; nt < 4; nt++) {
        int c = ncol + nt*8 + 2*tig;
        size_t o0 = (size_t)(q0 + mrow + grp) * DIMC + c;
        size_t o1 = (size_t)(q0 + mrow + grp + 8) * DIMC + c;
        *(float2*)(Ob + o0) = make_float2(accO[nt][0]*li0, accO[nt][1]*li0);
        *(float2*)(Ob + o1) = make_float2(accO[nt][2]*li1, accO[nt][3]*li1);
    }
}

// ---------------- gating: softmax over 8, top-2 ------------------------------
__global__ void gate_kernel(const float* __restrict__ hn,
                            const float* __restrict__ gw) {
    int gt   = (blockIdx.x * blockDim.x + threadIdx.x) >> 5;
    int lane = threadIdx.x & 31;
    if (gt >= NTOK) return;
    const float* row = hn + (size_t)gt * DIMC;
    float vals[32];
#pragma unroll
    for (int i = 0; i < 32; i++) vals[i] = row[lane + 32*i];
    float logits[EXPN];
#pragma unroll
    for (int e = 0; e < EXPN; e++) {
        const float* we = gw + e * DIMC;
        float s = 0.f;
#pragma unroll
        for (int i = 0; i < 32; i++) s += vals[i] * we[lane + 32*i];
        s += __shfl_xor_sync(0xffffffffu, s, 16);
        s += __shfl_xor_sync(0xffffffffu, s, 8);
        s += __shfl_xor_sync(0xffffffffu, s, 4);
        s += __shfl_xor_sync(0xffffffffu, s, 2);
        s += __shfl_xor_sync(0xffffffffu, s, 1);
        logits[e] = s;
    }
    if (lane == 0) {
        float mx = logits[0];
#pragma unroll
        for (int e = 1; e < EXPN; e++) mx = fmaxf(mx, logits[e]);
        float p[EXPN], sum = 0.f;
#pragma unroll
        for (int e = 0; e < EXPN; e++) { p[e] = __expf(logits[e]-mx); sum += p[e]; }
        float inv = 1.f / sum;
#pragma unroll
        for (int e = 0; e < EXPN; e++) p[e] *= inv;
        int e0 = 0;
        for (int e = 1; e < EXPN; e++) if (p[e] > p[e0]) e0 = e;
        int e1 = (e0 == 0) ? 1 : 0;
        for (int e = 0; e < EXPN; e++) { if (e == e0) continue; if (p[e] > p[e1]) e1 = e; }
        g_tok_exp[gt*2+0] = e0;  g_tok_exp[gt*2+1] = e1;
        g_tok_w  [gt*2+0] = p[e0]; g_tok_w[gt*2+1] = p[e1];
        atomicAdd(&g_cnt[e0], 1);
        atomicAdd(&g_cnt[e1], 1);
    }
}

__global__ void zero_cnt_kernel() {
    if (threadIdx.x < EXPN) g_cnt[threadIdx.x] = 0;
}

__global__ void scan_kernel() {
    if (threadIdx.x == 0) {
        int o = 0;
        for (int e = 0; e < EXPN; e++) { g_off[e] = o; g_fill[e] = o; o += g_cnt[e]; }
        g_off[EXPN] = o;
    }
}

__global__ void scatter_kernel() {
    int t = blockIdx.x * blockDim.x + threadIdx.x;
    if (t >= NTOK) return;
#pragma unroll
    for (int k = 0; k < TOPK; k++) {
        int e = g_tok_exp[t*2+k];
        int slot = atomicAdd(&g_fill[e], 1);
        g_tok_order[slot] = t;
        g_row_of[t*2+k] = slot;
    }
}

// ---------------- elementwise silu(a)*b (in place into a) --------------------
__global__ void silumul_kernel(float* __restrict__ a, const float* __restrict__ b,
                               int n) {
    int i = blockIdx.x * blockDim.x + threadIdx.x;
    if (i < n) {
        float x = a[i];
        a[i] = (x / (1.f + __expf(-x))) * b[i];
    }
}

// ---------------- final combine ----------------------------------------------
__global__ void combine_kernel(float* __restrict__ out) {
    int i = blockIdx.x * blockDim.x + threadIdx.x;
    if (i >= NTOK*DIMC) return;
    int t = i >> 10, d = i & 1023;
    int s0 = g_row_of[t*2+0], s1 = g_row_of[t*2+1];
    float w0 = g_tok_w[t*2+0], w1 = g_tok_w[t*2+1];
    float y = w0 * g_eo[(size_t)s0*DIMC + d] + w1 * g_eo[(size_t)s1*DIMC + d];
    out[i] = g_h[i] + g_sh[i] + y;
}

// ---------------- host orchestration -----------------------------------------
extern "C" void kernel_launch(void* const* d_in, const int* in_sizes, int n_in,
                              void* d_out, int out_size) {
    const float* x    = (const float*)d_in[0];
    const float* freqs= (const float*)d_in[1];
    const float* anw  = (const float*)d_in[2];
    const float* wq   = (const float*)d_in[3];
    const float* wk   = (const float*)d_in[4];
    const float* wv   = (const float*)d_in[5];
    const float* wo   = (const float*)d_in[6];
    const float* fnw  = (const float*)d_in[7];
    const float* gw   = (const float*)d_in[8];
    const float* ew1  = (const float*)d_in[9];
    const float* ew2  = (const float*)d_in[10];
    const float* ew3  = (const float*)d_in[11];
    const float* sw1  = (const float*)d_in[12];
    const float* sw2  = (const float*)d_in[13];
    const float* sw3  = (const float*)d_in[14];
    float* out = (float*)d_out;

    float *xn, *q, *k, *v, *att, *h, *hn, *sh, *e1, *e3, *eo;
    cudaGetSymbolAddress((void**)&xn,  g_xn);
    cudaGetSymbolAddress((void**)&q,   g_q);
    cudaGetSymbolAddress((void**)&k,   g_k);
    cudaGetSymbolAddress((void**)&v,   g_v);
    cudaGetSymbolAddress((void**)&att, g_att);
    cudaGetSymbolAddress((void**)&h,   g_h);
    cudaGetSymbolAddress((void**)&hn,  g_hn);
    cudaGetSymbolAddress((void**)&sh,  g_sh);
    cudaGetSymbolAddress((void**)&e1,  g_e1);
    cudaGetSymbolAddress((void**)&e3,  g_e3);
    cudaGetSymbolAddress((void**)&eo,  g_eo);

    // stateless: set every call (idempotent, host-side, capture-legal)
    cudaFuncSetAttribute(gemm_tc<true>,
        cudaFuncAttributeMaxDynamicSharedMemorySize, SMEM_GM);
    cudaFuncSetAttribute(gemm_tc<false>,
        cudaFuncAttributeMaxDynamicSharedMemorySize, SMEM_GM);
    cudaFuncSetAttribute(gemm_tc_moe,
        cudaFuncAttributeMaxDynamicSharedMemorySize, SMEM_GM);
    cudaFuncSetAttribute(attn_tc,
        cudaFuncAttributeMaxDynamicSharedMemorySize, SMEM_ATT);

    dim3 gGemm(DIMC/128, NTOK/128);   // (8, 32)

    // attention sub-block (3xTF32: routing-critical accuracy)
    rmsnorm_kernel<<<NTOK, 256>>>(x, anw, xn);
    gemm_tc<true><<<gGemm, 256, SMEM_GM>>>(xn, wq, q, nullptr, NTOK, DIMC, DIMC);
    gemm_tc<true><<<gGemm, 256, SMEM_GM>>>(xn, wk, k, nullptr, NTOK, DIMC, DIMC);
    gemm_tc<true><<<gGemm, 256, SMEM_GM>>>(xn, wv, v, nullptr, NTOK, DIMC, DIMC);
    rope_kernel<<<(NTOK*NHC*32 + 255)/256, 256>>>(q, k, freqs);
    attn_tc<<<dim3(SEQ/64, BATCH*NHC), 256, SMEM_ATT>>>(q, k, v, att);
    gemm_tc<true><<<gGemm, 256, SMEM_GM>>>(att, wo, h, x, NTOK, DIMC, DIMC);

    // MoE sub-block
    rmsnorm_kernel<<<NTOK, 256>>>(h, fnw, hn);
    zero_cnt_kernel<<<1, 32>>>();
    gate_kernel<<<NTOK/8, 256>>>(hn, gw);
    scan_kernel<<<1, 32>>>();
    scatter_kernel<<<NTOK/256, 256>>>();

    dim3 gMoe1(HIDC/128, NROUTED/128, EXPN);
    gemm_tc_moe<<<gMoe1, 256, SMEM_GM>>>(hn, ew1, e1, 1, HIDC, DIMC);
    gemm_tc_moe<<<gMoe1, 256, SMEM_GM>>>(hn, ew3, e3, 1, HIDC, DIMC);
    silumul_kernel<<<(NROUTED*HIDC)/256, 256>>>(e1, e3, NROUTED*HIDC);
    dim3 gMoe2(DIMC/128, NROUTED/128, EXPN);
    gemm_tc_moe<<<gMoe2, 256, SMEM_GM>>>(e1, ew2, eo, 0, DIMC, HIDC);

    // shared expert (single-pass TF32; output-only path)
    gemm_tc<false><<<gGemm, 256, SMEM_GM>>>(hn, sw1, q, nullptr, NTOK, DIMC, DIMC);
    gemm_tc<false><<<gGemm, 256, SMEM_GM>>>(hn, sw3, k, nullptr, NTOK, DIMC, DIMC);
    silumul_kernel<<<(NTOK*DIMC)/256, 256>>>(q, k, NTOK*DIMC);
    gemm_tc<false><<<gGemm, 256, SMEM_GM>>>(q, sw2, sh, nullptr, NTOK, DIMC, DIMC);

    combine_kernel<<<(NTOK*DIMC)/256, 256>>>(out);
}